// round 1
// baseline (speedup 1.0000x reference)
#include <cuda_runtime.h>
#include <cuda_bf16.h>
#include <math.h>

#define EPS_C (1.0f/137.0f)

// Problem constants
#define BATCH 2
#define TT 1024
#define CC 1024
#define F_QKV 3072
#define MROWS (BATCH*TT)     // 2048
#define NHEADS_EFF 64        // attention runs over d axis (64 "heads")
#define HD_EFF 16            // with inner dim 16

// Scratch (device globals; no allocation allowed)
__device__ float g_q[BATCH*NHEADS_EFF*TT*HD_EFF];   // [b,d,t,h]
__device__ float g_k[BATCH*NHEADS_EFF*TT*HD_EFF];
__device__ float g_v[BATCH*NHEADS_EFF*TT*HD_EFF];
__device__ float g_att[MROWS*CC];                   // attention output [b*t, c]
__device__ float g_x2a[MROWS];                      // ||x row||^2
__device__ float g_x2b[MROWS];                      // ||att row||^2
__device__ float g_k2a[F_QKV];                      // ||w_qkv col||^2
__device__ float g_k2b[CC];                         // ||w_proj col||^2

// ---------------- row norms ----------------
__global__ void rownorm_kernel(const float* __restrict__ src, int which) {
    int row = blockIdx.x;
    const float* base = (which ? &g_att[0] : src) + (size_t)row * CC;
    float s = 0.f;
    for (int c = threadIdx.x; c < CC; c += 256) {
        float v = base[c];
        s = fmaf(v, v, s);
    }
    // warp reduce
    #pragma unroll
    for (int off = 16; off; off >>= 1) s += __shfl_xor_sync(~0u, s, off);
    __shared__ float red[8];
    if ((threadIdx.x & 31) == 0) red[threadIdx.x >> 5] = s;
    __syncthreads();
    if (threadIdx.x == 0) {
        float t = 0.f;
        #pragma unroll
        for (int i = 0; i < 8; i++) t += red[i];
        (which ? g_x2b : g_x2a)[row] = t;
    }
}

// ---------------- col norms ----------------
__global__ void colnorm_kernel(const float* __restrict__ w, int N, int which) {
    int f = blockIdx.x * 256 + threadIdx.x;
    if (f >= N) return;
    float s = 0.f;
    #pragma unroll 8
    for (int c = 0; c < CC; c++) {
        float v = w[(size_t)c * N + f];
        s = fmaf(v, v, s);
    }
    (which ? g_k2b : g_k2a)[f] = s;
}

// ---------------- SGEMM + YAT epilogue ----------------
// C[m,n] = yat( sum_k A[m,k]*B[k,n] )
// mode 0: A = x, norms (g_x2a, g_k2a), scatter into g_q/g_k/g_v
// mode 1: A = g_att, norms (g_x2b, g_k2b), write outP
#define BM 128
#define BN 128
#define BK 16
__global__ __launch_bounds__(256)
void gemm_yat_kernel(const float* __restrict__ Ain, const float* __restrict__ Bmat,
                     const float* __restrict__ bias, const float* __restrict__ alpha,
                     int N, int mode, float* __restrict__ outP) {
    __shared__ float As[BK][BM];
    __shared__ float Bs[BK][BN];
    const int tid = threadIdx.x;
    const int br = blockIdx.y, bc = blockIdx.x;
    const int K = CC;
    const float* A = (mode == 0) ? Ain : &g_att[0];
    const float* Ab = A + (size_t)br * BM * K;
    const float* Bb = Bmat + (size_t)bc * BN;

    float acc[8][8];
    #pragma unroll
    for (int i = 0; i < 8; i++)
        #pragma unroll
        for (int j = 0; j < 8; j++) acc[i][j] = 0.f;

    const int arow = tid >> 2;          // 0..63
    const int acol = (tid & 3) << 2;    // 0,4,8,12
    const int brow = tid >> 5;          // 0..7
    const int bcol = (tid & 31) << 2;   // 0..124

    const int tr = (tid >> 4) << 3;     // 0..120
    const int tc = (tid & 15) << 3;     // 0..120

    for (int k0 = 0; k0 < K; k0 += BK) {
        #pragma unroll
        for (int r = 0; r < 2; r++) {
            int row = arow + r * 64;
            float4 a4 = *(const float4*)(Ab + (size_t)row * K + k0 + acol);
            As[acol + 0][row] = a4.x;
            As[acol + 1][row] = a4.y;
            As[acol + 2][row] = a4.z;
            As[acol + 3][row] = a4.w;
        }
        #pragma unroll
        for (int r = 0; r < 2; r++) {
            int row = brow + r * 8;
            float4 b4 = *(const float4*)(Bb + (size_t)(k0 + row) * N + bcol);
            *(float4*)&Bs[row][bcol] = b4;
        }
        __syncthreads();
        #pragma unroll
        for (int k = 0; k < BK; k++) {
            float ra[8], rb[8];
            *(float4*)&ra[0] = *(const float4*)&As[k][tr];
            *(float4*)&ra[4] = *(const float4*)&As[k][tr + 4];
            *(float4*)&rb[0] = *(const float4*)&Bs[k][tc];
            *(float4*)&rb[4] = *(const float4*)&Bs[k][tc + 4];
            #pragma unroll
            for (int i = 0; i < 8; i++)
                #pragma unroll
                for (int j = 0; j < 8; j++)
                    acc[i][j] = fmaf(ra[i], rb[j], acc[i][j]);
        }
        __syncthreads();
    }

    const float scale = powf(sqrtf((float)N) / log1pf((float)N), alpha[0]);
    const float* x2 = (mode == 0) ? &g_x2a[0] : &g_x2b[0];
    const float* k2 = (mode == 0) ? &g_k2a[0] : &g_k2b[0];

    #pragma unroll
    for (int i = 0; i < 8; i++) {
        int gm = br * BM + tr + i;
        float x2v = x2[gm];
        int b = gm >> 10, t = gm & 1023;
        #pragma unroll
        for (int j = 0; j < 8; j++) {
            int gn = bc * BN + tc + j;
            float y = acc[i][j];
            float val = (y * y) / (x2v + k2[gn] - 2.f * y + EPS_C) * scale + bias[gn];
            if (mode == 0) {
                int s = gn >> 10;
                int h = (gn & 1023) >> 6;
                int dd = gn & 63;
                size_t idx = (((size_t)(b * NHEADS_EFF + dd) * TT) + t) * HD_EFF + h;
                if (s == 0) g_q[idx] = val;
                else if (s == 1) g_k[idx] = val;
                else g_v[idx] = val;
            } else {
                outP[(size_t)gm * N + gn] = val;
            }
        }
    }
}

// ---------------- attention ----------------
// grid: (128 row-tiles, 64 d, 2 b); block: 256 = 8 warps, 1 query row per warp
__global__ __launch_bounds__(256)
void attn_kernel(const float* __restrict__ alpha_attn) {
    const int lane = threadIdx.x & 31;
    const int w = threadIdx.x >> 5;
    const int it = blockIdx.x;
    const int d = blockIdx.y;
    const int b = blockIdx.z;
    const int i = it * 8 + w;
    const int tid = threadIdx.x;

    __shared__ float Kt[64][20];
    __shared__ float Vt[64][20];
    __shared__ float k2s[64];

    const float inv_scale = powf(64.0f / log1pf(64.0f), alpha_attn[0]);

    const size_t headbase = (size_t)(b * NHEADS_EFF + d) * TT * HD_EFF;
    const float* qb = g_q + headbase;
    const float* kb = g_k + headbase;
    const float* vb = g_v + headbase;

    float q[16];
    #pragma unroll
    for (int e = 0; e < 16; e += 4) {
        float4 q4 = *(const float4*)(qb + (size_t)i * 16 + e);
        q[e] = q4.x; q[e + 1] = q4.y; q[e + 2] = q4.z; q[e + 3] = q4.w;
    }
    float q2 = 0.f;
    #pragma unroll
    for (int e = 0; e < 16; e++) q2 = fmaf(q[e], q[e], q2);

    float m = -1e30f, l = 0.f;
    float acc[16];
    #pragma unroll
    for (int e = 0; e < 16; e++) acc[e] = 0.f;

    const int jt_max = (it * 8 + 7) >> 6;
    for (int jt = 0; jt <= jt_max; jt++) {
        // cooperative tile load: 64x16 each of K,V (256 float4's each)
        {
            int jj = tid >> 2, ee = (tid & 3) << 2;
            float4 k4 = ((const float4*)(kb + (size_t)jt * 64 * 16))[tid];
            Kt[jj][ee + 0] = k4.x; Kt[jj][ee + 1] = k4.y; Kt[jj][ee + 2] = k4.z; Kt[jj][ee + 3] = k4.w;
            float4 v4 = ((const float4*)(vb + (size_t)jt * 64 * 16))[tid];
            Vt[jj][ee + 0] = v4.x; Vt[jj][ee + 1] = v4.y; Vt[jj][ee + 2] = v4.z; Vt[jj][ee + 3] = v4.w;
        }
        __syncthreads();
        if (tid < 64) {
            float s = 0.f;
            #pragma unroll
            for (int h = 0; h < 16; h++) s = fmaf(Kt[tid][h], Kt[tid][h], s);
            k2s[tid] = s;
        }
        __syncthreads();

        #pragma unroll
        for (int sub = 0; sub < 2; sub++) {
            int j = lane + sub * 32;
            int jg = jt * 64 + j;
            if (jg <= i) {
                float kr[16];
                #pragma unroll
                for (int e = 0; e < 16; e += 4) {
                    float4 k4 = *(const float4*)&Kt[j][e];
                    kr[e] = k4.x; kr[e + 1] = k4.y; kr[e + 2] = k4.z; kr[e + 3] = k4.w;
                }
                float s = 0.f;
                #pragma unroll
                for (int h = 0; h < 16; h++) s = fmaf(q[h], kr[h], s);
                float den = q2 + k2s[j] - 2.f * s + EPS_C;
                float a = (s * s) / den * inv_scale;
                if (a > m) {
                    float c = __expf(m - a);
                    l *= c;
                    #pragma unroll
                    for (int e = 0; e < 16; e++) acc[e] *= c;
                    m = a;
                }
                float p = __expf(a - m);
                l += p;
                #pragma unroll
                for (int e = 0; e < 16; e += 4) {
                    float4 v4 = *(const float4*)&Vt[j][e];
                    acc[e]     = fmaf(p, v4.x, acc[e]);
                    acc[e + 1] = fmaf(p, v4.y, acc[e + 1]);
                    acc[e + 2] = fmaf(p, v4.z, acc[e + 2]);
                    acc[e + 3] = fmaf(p, v4.w, acc[e + 3]);
                }
            }
        }
        __syncthreads();
    }

    // butterfly merge of per-lane softmax states
    #pragma unroll
    for (int off = 16; off > 0; off >>= 1) {
        float mo = __shfl_xor_sync(~0u, m, off);
        float lo = __shfl_xor_sync(~0u, l, off);
        float mn = fmaxf(m, mo);
        float cs = __expf(m - mn);
        float co = __expf(mo - mn);
        l = l * cs + lo * co;
        #pragma unroll
        for (int e = 0; e < 16; e++) {
            float ao = __shfl_xor_sync(~0u, acc[e], off);
            acc[e] = acc[e] * cs + ao * co;
        }
        m = mn;
    }

    if (lane == 0) {
        float invl = 1.f / l;
        float* outp = &g_att[((size_t)(b * TT + i)) * CC + d * 16];
        #pragma unroll
        for (int e = 0; e < 16; e++) outp[e] = acc[e] * invl;
    }
}

// ---------------- launch ----------------
extern "C" void kernel_launch(void* const* d_in, const int* in_sizes, int n_in,
                              void* d_out, int out_size) {
    const float* x          = (const float*)d_in[0];
    // d_in[1] = mask (causal; implicit)
    const float* w_qkv      = (const float*)d_in[2];
    const float* b_qkv      = (const float*)d_in[3];
    const float* alpha_qkv  = (const float*)d_in[4];
    const float* w_proj     = (const float*)d_in[5];
    const float* b_proj     = (const float*)d_in[6];
    const float* alpha_proj = (const float*)d_in[7];
    const float* alpha_attn = (const float*)d_in[8];
    float* out = (float*)d_out;

    // norms for qkv yat
    rownorm_kernel<<<MROWS, 256>>>(x, 0);
    colnorm_kernel<<<F_QKV / 256, 256>>>(w_qkv, F_QKV, 0);
    colnorm_kernel<<<CC / 256, 256>>>(w_proj, CC, 1);

    // qkv GEMM + yat + scatter to [b,d,t,h]
    {
        dim3 grid(F_QKV / BN, MROWS / BM);
        gemm_yat_kernel<<<grid, 256>>>(x, w_qkv, b_qkv, alpha_qkv, F_QKV, 0, nullptr);
    }

    // attention
    {
        dim3 grid(TT / 8, NHEADS_EFF, BATCH);
        attn_kernel<<<grid, 256>>>(alpha_attn);
    }

    // norms for proj yat
    rownorm_kernel<<<MROWS, 256>>>(nullptr, 1);

    // proj GEMM + yat -> out
    {
        dim3 grid(CC / BN, MROWS / BM);
        gemm_yat_kernel<<<grid, 256>>>(nullptr, w_proj, b_proj, alpha_proj, CC, 1, out);
    }
}

// round 2
// speedup vs baseline: 1.2965x; 1.2965x over previous
#include <cuda_runtime.h>
#include <cuda_bf16.h>
#include <math.h>

#define EPS_C (1.0f/137.0f)

#define BATCH 2
#define TT 1024
#define CC 1024
#define F_QKV 3072
#define MROWS (BATCH*TT)
#define NHEADS_EFF 64
#define HD_EFF 16

typedef unsigned long long u64;

// ---------------- scratch ----------------
__device__ float g_q[BATCH*NHEADS_EFF*TT*HD_EFF];
__device__ float g_k[BATCH*NHEADS_EFF*TT*HD_EFF];
__device__ float g_v[BATCH*NHEADS_EFF*TT*HD_EFF];
__device__ float g_att[MROWS*CC];
__device__ float g_x2a[MROWS];
__device__ float g_x2b[MROWS];
__device__ float g_k2a[F_QKV];
__device__ float g_k2b[CC];
__device__ float g_kk[BATCH*NHEADS_EFF*TT];   // ||k row||^2 in attention layout

// ---------------- f32x2 helpers ----------------
__device__ __forceinline__ u64 pk2(float x, float y) {
    u64 r; asm("mov.b64 %0,{%1,%2};" : "=l"(r) : "f"(x), "f"(y)); return r;
}
__device__ __forceinline__ void upk2(u64 v, float& x, float& y) {
    asm("mov.b64 {%0,%1},%2;" : "=f"(x), "=f"(y) : "l"(v));
}
__device__ __forceinline__ u64 ffma2(u64 a, u64 b, u64 c) {
    u64 d; asm("fma.rn.f32x2 %0,%1,%2,%3;" : "=l"(d) : "l"(a), "l"(b), "l"(c)); return d;
}
__device__ __forceinline__ u64 fmul2(u64 a, u64 b) {
    u64 d; asm("mul.rn.f32x2 %0,%1,%2;" : "=l"(d) : "l"(a), "l"(b)); return d;
}
__device__ __forceinline__ unsigned smem_u32(const void* p) {
    return (unsigned)__cvta_generic_to_shared(p);
}
__device__ __forceinline__ void cp_async16(unsigned dst, const void* src) {
    asm volatile("cp.async.cg.shared.global [%0], [%1], 16;" :: "r"(dst), "l"(src));
}
__device__ __forceinline__ void cp_commit() { asm volatile("cp.async.commit_group;"); }
__device__ __forceinline__ void cp_wait0()  { asm volatile("cp.async.wait_group 0;"); }

// ---------------- row norms ----------------
__global__ void rownorm_kernel(const float* __restrict__ src, int which) {
    int row = blockIdx.x;
    const float* base = (which ? &g_att[0] : src) + (size_t)row * CC;
    float s = 0.f;
    for (int c = threadIdx.x; c < CC; c += 256) {
        float v = base[c];
        s = fmaf(v, v, s);
    }
    #pragma unroll
    for (int off = 16; off; off >>= 1) s += __shfl_xor_sync(~0u, s, off);
    __shared__ float red[8];
    if ((threadIdx.x & 31) == 0) red[threadIdx.x >> 5] = s;
    __syncthreads();
    if (threadIdx.x == 0) {
        float t = 0.f;
        #pragma unroll
        for (int i = 0; i < 8; i++) t += red[i];
        (which ? g_x2b : g_x2a)[row] = t;
    }
}

// ---------------- col norms ----------------
__global__ void colnorm_kernel(const float* __restrict__ w, int N, int which) {
    int f = blockIdx.x * 256 + threadIdx.x;
    if (f >= N) return;
    float s = 0.f;
    #pragma unroll 8
    for (int c = 0; c < CC; c++) {
        float v = w[(size_t)c * N + f];
        s = fmaf(v, v, s);
    }
    (which ? g_k2b : g_k2a)[f] = s;
}

// ---------------- k row norms (attention layout) ----------------
__global__ void kk_kernel() {
    int r = blockIdx.x * 256 + threadIdx.x;   // 0..131071
    const float4* p = (const float4*)(g_k + (size_t)r * 16);
    float4 a = p[0], b = p[1], c = p[2], d = p[3];
    float s = a.x*a.x + a.y*a.y + a.z*a.z + a.w*a.w
            + b.x*b.x + b.y*b.y + b.z*b.z + b.w*b.w
            + c.x*c.x + c.y*c.y + c.z*c.z + c.w*c.w
            + d.x*d.x + d.y*d.y + d.z*d.z + d.w*d.w;
    g_kk[r] = s;
}

// ---------------- SGEMM (f32x2) + YAT epilogue ----------------
#define BM 128
#define BN 128
#define BK 16
#define NT (CC/BK)   // 64 k-tiles
__global__ __launch_bounds__(256, 2)
void gemm_yat_kernel(const float* __restrict__ Ain, const float* __restrict__ Bmat,
                     const float* __restrict__ bias, const float* __restrict__ alpha,
                     int N, int mode, float* __restrict__ outP) {
    __shared__ u64   As2[2][BK][BM];   // duplicated (a,a) pairs
    __shared__ float Bs[2][BK][BN];

    const int tid = threadIdx.x;
    const int br = blockIdx.y, bc = blockIdx.x;
    const int K = CC;
    const float* A = (mode == 0) ? Ain : &g_att[0];
    const float* Ab = A + (size_t)br * BM * K;
    const float* Bb = Bmat + (size_t)bc * BN;

    u64 acc2[8][4];
    #pragma unroll
    for (int i = 0; i < 8; i++)
        #pragma unroll
        for (int j = 0; j < 4; j++) acc2[i][j] = 0ull;

    // A tile: thread loads row (tid>>1), 8 floats at (tid&1)*8
    const int am = tid >> 1;
    const int ak = (tid & 1) * 8;
    // B tile: thread cp.asyncs row (tid>>4), 32 bytes at (tid&15)*8 floats
    const int brow = tid >> 4;
    const int bcol = (tid & 15) * 8;

    const int tr = (tid >> 4) << 3;
    const int tc = (tid & 15) << 3;

    float af[8];
    // ---- prologue: tile 0 ----
    {
        float4 v0 = *(const float4*)(Ab + (size_t)am * K + ak);
        float4 v1 = *(const float4*)(Ab + (size_t)am * K + ak + 4);
        *(float4*)&af[0] = v0; *(float4*)&af[4] = v1;
        #pragma unroll
        for (int e = 0; e < 8; e++) As2[0][ak + e][am] = pk2(af[e], af[e]);
        cp_async16(smem_u32(&Bs[0][brow][bcol]),     Bb + (size_t)brow * N + bcol);
        cp_async16(smem_u32(&Bs[0][brow][bcol + 4]), Bb + (size_t)brow * N + bcol + 4);
        cp_commit();
    }

    for (int kt = 0; kt < NT; kt++) {
        const int cur = kt & 1, nxt = cur ^ 1;
        cp_wait0();
        __syncthreads();
        // prefetch next tile
        if (kt < NT - 1) {
            int k0 = (kt + 1) * BK;
            float4 v0 = *(const float4*)(Ab + (size_t)am * K + k0 + ak);
            float4 v1 = *(const float4*)(Ab + (size_t)am * K + k0 + ak + 4);
            *(float4*)&af[0] = v0; *(float4*)&af[4] = v1;
            cp_async16(smem_u32(&Bs[nxt][brow][bcol]),     Bb + (size_t)(k0 + brow) * N + bcol);
            cp_async16(smem_u32(&Bs[nxt][brow][bcol + 4]), Bb + (size_t)(k0 + brow) * N + bcol + 4);
            cp_commit();
        }
        // compute current tile
        #pragma unroll
        for (int k = 0; k < BK; k++) {
            const ulonglong2* bp = (const ulonglong2*)&Bs[cur][k][tc];
            ulonglong2 u0 = bp[0], u1 = bp[1];
            u64 rb0 = u0.x, rb1 = u0.y, rb2v = u1.x, rb3 = u1.y;
            #pragma unroll
            for (int i = 0; i < 8; i++) {
                u64 a2 = As2[cur][k][tr + i];
                acc2[i][0] = ffma2(a2, rb0,  acc2[i][0]);
                acc2[i][1] = ffma2(a2, rb1,  acc2[i][1]);
                acc2[i][2] = ffma2(a2, rb2v, acc2[i][2]);
                acc2[i][3] = ffma2(a2, rb3,  acc2[i][3]);
            }
        }
        if (kt < NT - 1) {
            #pragma unroll
            for (int e = 0; e < 8; e++) As2[nxt][ak + e][am] = pk2(af[e], af[e]);
        }
    }

    // ---- YAT epilogue ----
    const float scale = powf(sqrtf((float)N) / log1pf((float)N), alpha[0]);
    const float* x2 = (mode == 0) ? &g_x2a[0] : &g_x2b[0];
    const float* k2 = (mode == 0) ? &g_k2a[0] : &g_k2b[0];

    #pragma unroll
    for (int i = 0; i < 8; i++) {
        int gm = br * BM + tr + i;
        float x2v = x2[gm];
        int b = gm >> 10, t = gm & 1023;
        #pragma unroll
        for (int j2 = 0; j2 < 4; j2++) {
            float y0, y1;
            upk2(acc2[i][j2], y0, y1);
            #pragma unroll
            for (int h = 0; h < 2; h++) {
                float y = h ? y1 : y0;
                int gn = bc * BN + tc + j2 * 2 + h;
                float val = (y * y) / (x2v + k2[gn] - 2.f * y + EPS_C) * scale + bias[gn];
                if (mode == 0) {
                    int s = gn >> 10;
                    int hh = (gn & 1023) >> 6;
                    int dd = gn & 63;
                    size_t idx = (((size_t)(b * NHEADS_EFF + dd) * TT) + t) * HD_EFF + hh;
                    if (s == 0) g_q[idx] = val;
                    else if (s == 1) g_k[idx] = val;
                    else g_v[idx] = val;
                } else {
                    outP[(size_t)gm * N + gn] = val;
                }
            }
        }
    }
}

// ---------------- attention ----------------
// lane owns query row i; K/V broadcast from smem; no-max softmax (scores >= 0, tiny)
#define AJT 128
__global__ __launch_bounds__(256)
void attn_kernel(const float* __restrict__ alpha_attn) {
    __shared__ float Kt[AJT * 16];
    __shared__ float Vt[AJT * 16];
    __shared__ float K2t[AJT];

    const int tid = threadIdx.x;
    const int lane = tid & 31;
    const int w = tid >> 5;
    const int chunk = blockIdx.x;     // 0..3 (256 i's each)
    const int d = blockIdx.y;
    const int b = blockIdx.z;
    const int i = chunk * 256 + w * 32 + lane;

    const float inv_scale = powf(64.0f / log1pf(64.0f), alpha_attn[0]);
    const size_t hb = (size_t)(b * NHEADS_EFF + d) * TT * HD_EFF;

    // q row in registers as f32x2 pairs
    u64 qq[8];
    {
        const ulonglong2* qp = (const ulonglong2*)(g_q + hb + (size_t)i * 16);
        #pragma unroll
        for (int e = 0; e < 4; e++) {
            ulonglong2 u = qp[e];
            qq[e * 2] = u.x; qq[e * 2 + 1] = u.y;
        }
    }
    float q2;
    {
        u64 s2 = 0ull;
        #pragma unroll
        for (int e = 0; e < 8; e++) s2 = ffma2(qq[e], qq[e], s2);
        float lo, hi; upk2(s2, lo, hi);
        q2 = lo + hi + EPS_C;
    }

    u64 acc[8];
    #pragma unroll
    for (int e = 0; e < 8; e++) acc[e] = 0ull;
    float l = 0.f;

    const int n_st = 2 * chunk + 2;
    for (int st = 0; st < n_st; st++) {
        __syncthreads();
        // stage K/V tile + k2
        {
            const float4* ks = (const float4*)(g_k + hb + (size_t)st * AJT * 16);
            const float4* vs = (const float4*)(g_v + hb + (size_t)st * AJT * 16);
            ((float4*)Kt)[tid]       = ks[tid];
            ((float4*)Kt)[tid + 256] = ks[tid + 256];
            ((float4*)Vt)[tid]       = vs[tid];
            ((float4*)Vt)[tid + 256] = vs[tid + 256];
            if (tid < AJT) K2t[tid] = g_kk[(size_t)(b * NHEADS_EFF + d) * TT + st * AJT + tid];
        }
        __syncthreads();

        int lim = chunk * 256 + w * 32 + 32 - st * AJT;
        if (lim > AJT) lim = AJT;
        const int jb = st * AJT;
        #pragma unroll 2
        for (int jj = 0; jj < lim; jj++) {
            const u64* kp = (const u64*)&Kt[jj * 16];
            u64 s2 = 0ull;
            #pragma unroll
            for (int e = 0; e < 8; e++) s2 = ffma2(qq[e], kp[e], s2);
            float lo, hi; upk2(s2, lo, hi);
            float s = lo + hi;
            float den = fmaf(-2.f, s, q2 + K2t[jj]);
            float a = __fdividef(s * s * inv_scale, den);
            float p = __expf(a);
            if (jb + jj > i) p = 0.f;
            l += p;
            u64 pp = pk2(p, p);
            const u64* vp = (const u64*)&Vt[jj * 16];
            #pragma unroll
            for (int e = 0; e < 8; e++) acc[e] = ffma2(pp, vp[e], acc[e]);
        }
    }

    // normalize + write
    float invl = 1.0f / l;
    u64 iv = pk2(invl, invl);
    ulonglong2* outp = (ulonglong2*)(&g_att[((size_t)(b * TT + i)) * CC + d * 16]);
    #pragma unroll
    for (int e = 0; e < 4; e++) {
        ulonglong2 u;
        u.x = fmul2(acc[e * 2], iv);
        u.y = fmul2(acc[e * 2 + 1], iv);
        outp[e] = u;
    }
}

// ---------------- launch ----------------
extern "C" void kernel_launch(void* const* d_in, const int* in_sizes, int n_in,
                              void* d_out, int out_size) {
    const float* x          = (const float*)d_in[0];
    const float* w_qkv      = (const float*)d_in[2];
    const float* b_qkv      = (const float*)d_in[3];
    const float* alpha_qkv  = (const float*)d_in[4];
    const float* w_proj     = (const float*)d_in[5];
    const float* b_proj     = (const float*)d_in[6];
    const float* alpha_proj = (const float*)d_in[7];
    const float* alpha_attn = (const float*)d_in[8];
    float* out = (float*)d_out;

    rownorm_kernel<<<MROWS, 256>>>(x, 0);
    colnorm_kernel<<<F_QKV / 256, 256>>>(w_qkv, F_QKV, 0);
    colnorm_kernel<<<CC / 256, 256>>>(w_proj, CC, 1);

    {
        dim3 grid(F_QKV / BN, MROWS / BM);
        gemm_yat_kernel<<<grid, 256>>>(x, w_qkv, b_qkv, alpha_qkv, F_QKV, 0, nullptr);
    }

    kk_kernel<<<(BATCH * NHEADS_EFF * TT) / 256, 256>>>();

    {
        dim3 grid(TT / 256, NHEADS_EFF, BATCH);
        attn_kernel<<<grid, 256>>>(alpha_attn);
    }

    rownorm_kernel<<<MROWS, 256>>>(nullptr, 1);

    {
        dim3 grid(CC / BN, MROWS / BM);
        gemm_yat_kernel<<<grid, 256>>>(nullptr, w_proj, b_proj, alpha_proj, CC, 1, out);
    }
}

// round 4
// speedup vs baseline: 1.6995x; 1.3108x over previous
#include <cuda_runtime.h>
#include <cuda_bf16.h>
#include <math.h>
#include <stdint.h>

#define EPS_C (1.0f/137.0f)

#define BATCH 2
#define TT 1024
#define CC 1024
#define F_QKV 3072
#define MROWS (BATCH*TT)
#define NHEADS_EFF 64
#define HD_EFF 16

typedef unsigned long long u64;

// ---------------- scratch ----------------
__device__ float g_q[BATCH*NHEADS_EFF*TT*HD_EFF];
__device__ float g_k[BATCH*NHEADS_EFF*TT*HD_EFF];
__device__ float g_v[BATCH*NHEADS_EFF*TT*HD_EFF];
__device__ float g_att[MROWS*CC];
__device__ float g_x2a[MROWS];
__device__ float g_x2b[MROWS];
__device__ float g_k2a[F_QKV];
__device__ float g_k2b[CC];
__device__ float g_kk[BATCH*NHEADS_EFF*TT];

__device__ __nv_bfloat16 g_ahi[MROWS*CC];
__device__ __nv_bfloat16 g_alo[MROWS*CC];
__device__ __nv_bfloat16 g_bqhi[F_QKV*CC];   // transposed [N,K]
__device__ __nv_bfloat16 g_bqlo[F_QKV*CC];
__device__ __nv_bfloat16 g_bphi[CC*CC];
__device__ __nv_bfloat16 g_bplo[CC*CC];

// ---------------- helpers ----------------
__device__ __forceinline__ u64 pk2(float x, float y) {
    u64 r; asm("mov.b64 %0,{%1,%2};" : "=l"(r) : "f"(x), "f"(y)); return r;
}
__device__ __forceinline__ void upk2(u64 v, float& x, float& y) {
    asm("mov.b64 {%0,%1},%2;" : "=f"(x), "=f"(y) : "l"(v));
}
__device__ __forceinline__ u64 ffma2(u64 a, u64 b, u64 c) {
    u64 d; asm("fma.rn.f32x2 %0,%1,%2,%3;" : "=l"(d) : "l"(a), "l"(b), "l"(c)); return d;
}
__device__ __forceinline__ u64 fmul2(u64 a, u64 b) {
    u64 d; asm("mul.rn.f32x2 %0,%1,%2;" : "=l"(d) : "l"(a), "l"(b)); return d;
}
__device__ __forceinline__ unsigned smem_u32(const void* p) {
    return (unsigned)__cvta_generic_to_shared(p);
}
__device__ __forceinline__ void cp_async16(unsigned dst, const void* src) {
    asm volatile("cp.async.cg.shared.global [%0], [%1], 16;" :: "r"(dst), "l"(src));
}
__device__ __forceinline__ void cp_commit() { asm volatile("cp.async.commit_group;"); }
__device__ __forceinline__ void cp_wait0()  { asm volatile("cp.async.wait_group 0;"); }
__device__ __forceinline__ void cp_wait1()  { asm volatile("cp.async.wait_group 1;"); }

__device__ __forceinline__ void ldsm4(uint32_t* r, uint32_t addr) {
    asm volatile("ldmatrix.sync.aligned.m8n8.x4.shared.b16 {%0,%1,%2,%3},[%4];"
        : "=r"(r[0]), "=r"(r[1]), "=r"(r[2]), "=r"(r[3]) : "r"(addr));
}
__device__ __forceinline__ void mma16816(float* c, const uint32_t* a, const uint32_t* b) {
    asm volatile("mma.sync.aligned.m16n8k16.row.col.f32.bf16.bf16.f32 "
        "{%0,%1,%2,%3},{%4,%5,%6,%7},{%8,%9},{%0,%1,%2,%3};"
        : "+f"(c[0]), "+f"(c[1]), "+f"(c[2]), "+f"(c[3])
        : "r"(a[0]), "r"(a[1]), "r"(a[2]), "r"(a[3]), "r"(b[0]), "r"(b[1]));
}

// ---------------- row norms ----------------
__global__ void rownorm_kernel(const float* __restrict__ src, float* __restrict__ dst) {
    int row = blockIdx.x;
    const float* base = src + (size_t)row * CC;
    float s = 0.f;
    for (int c = threadIdx.x; c < CC; c += 256) {
        float v = base[c];
        s = fmaf(v, v, s);
    }
    #pragma unroll
    for (int off = 16; off; off >>= 1) s += __shfl_xor_sync(~0u, s, off);
    __shared__ float red[8];
    if ((threadIdx.x & 31) == 0) red[threadIdx.x >> 5] = s;
    __syncthreads();
    if (threadIdx.x == 0) {
        float t = 0.f;
        #pragma unroll
        for (int i = 0; i < 8; i++) t += red[i];
        dst[row] = t;
    }
}

// ---------------- col norms ----------------
__global__ void colnorm_kernel(const float* __restrict__ w, int N, float* __restrict__ dst) {
    int f = blockIdx.x * 256 + threadIdx.x;
    if (f >= N) return;
    float s = 0.f;
    #pragma unroll 8
    for (int c = 0; c < CC; c++) {
        float v = w[(size_t)c * N + f];
        s = fmaf(v, v, s);
    }
    dst[f] = s;
}

// ---------------- bf16 split (element-wise) ----------------
__global__ void split_kernel(const float* __restrict__ src,
                             __nv_bfloat16* __restrict__ hi, __nv_bfloat16* __restrict__ lo) {
    int i = blockIdx.x * 256 + threadIdx.x;
    float v = src[i];
    __nv_bfloat16 h = __float2bfloat16(v);
    float r = v - __bfloat162float(h);
    hi[i] = h;
    lo[i] = __float2bfloat16(r);
}

// ---------------- bf16 split + transpose: w[K,N] -> hiT/loT [N,K] ----------------
__global__ void tsplit_kernel(const float* __restrict__ w, int N,
                              __nv_bfloat16* __restrict__ hiT, __nv_bfloat16* __restrict__ loT) {
    __shared__ float tile[32][33];
    int n0 = blockIdx.x * 32, k0 = blockIdx.y * 32;
    int tx = threadIdx.x & 31, ty = threadIdx.x >> 5;
    #pragma unroll
    for (int r = 0; r < 32; r += 8)
        tile[ty + r][tx] = w[(size_t)(k0 + ty + r) * N + n0 + tx];
    __syncthreads();
    #pragma unroll
    for (int r = 0; r < 32; r += 8) {
        float v = tile[tx][ty + r];
        __nv_bfloat16 h = __float2bfloat16(v);
        float res = v - __bfloat162float(h);
        size_t idx = (size_t)(n0 + ty + r) * CC + k0 + tx;
        hiT[idx] = h;
        loT[idx] = __float2bfloat16(res);
    }
}

// ---------------- k row norms (attention layout) ----------------
__global__ void kk_kernel() {
    int r = blockIdx.x * 256 + threadIdx.x;
    const float4* p = (const float4*)(g_k + (size_t)r * 16);
    float4 a = p[0], b = p[1], c = p[2], d = p[3];
    float s = a.x*a.x + a.y*a.y + a.z*a.z + a.w*a.w
            + b.x*b.x + b.y*b.y + b.z*b.z + b.w*b.w
            + c.x*c.x + c.y*c.y + c.z*c.z + c.w*c.w
            + d.x*d.x + d.y*d.y + d.z*d.z + d.w*d.w;
    g_kk[r] = s;
}

// ---------------- mma.sync GEMM + YAT epilogue ----------------
// BM=128, BN=128, BK=32; 8 warps (2x4), warp tile 64x32.
// D = Ahi*Bhi + Ahi*Blo + Alo*Bhi (K-major both operands)
#define GBK 32
#define ROWPAD 40                 // halves per row (32 + 8 pad)
#define TILE_B (128*ROWPAD*2)     // 10240 bytes
#define BUF_B  (4*TILE_B)         // 40960
#define GDYN   (2*BUF_B)          // 81920

__global__ __launch_bounds__(256, 1)
void gemm_mma_kernel(const __nv_bfloat16* __restrict__ Ahi, const __nv_bfloat16* __restrict__ Alo,
                     const __nv_bfloat16* __restrict__ BhiT, const __nv_bfloat16* __restrict__ BloT,
                     const float* __restrict__ x2, const float* __restrict__ k2,
                     const float* __restrict__ bias, const float* __restrict__ alpha,
                     int N, int mode, float* __restrict__ outP) {
    extern __shared__ char smem[];
    const uint32_t sb = smem_u32(smem);
    const int tid = threadIdx.x;
    const int wid = tid >> 5, lane = tid & 31;
    const int wr = wid >> 2, wc = wid & 3;
    const int m0 = blockIdx.y * 128, n0 = blockIdx.x * 128;

    const __nv_bfloat16* srcs[4] = {
        Ahi + (size_t)m0 * CC, Alo + (size_t)m0 * CC,
        BhiT + (size_t)n0 * CC, BloT + (size_t)n0 * CC };

    // cp.async mapping: 2048 16B-chunks per buffer; 8 per thread
    // chunk id = t4*512 + r*4 + c
    float acc[4][4][4];
    #pragma unroll
    for (int i = 0; i < 4; i++)
        #pragma unroll
        for (int j = 0; j < 4; j++)
            #pragma unroll
            for (int e = 0; e < 4; e++) acc[i][j][e] = 0.f;

    const int grp = lane >> 3;
    // ldmatrix per-thread byte offsets
    const uint32_t aRow = (uint32_t)((wr*64 + (grp&1)*8 + (lane&7)) * (ROWPAD*2) + (grp>>1)*16);
    const uint32_t bRow = (uint32_t)((wc*32 + (grp>>1)*8 + (lane&7)) * (ROWPAD*2) + (grp&1)*16);

    const int NT = CC / GBK;   // 32

    // prologue: tile 0
    {
        const uint32_t bufb = sb;
        #pragma unroll
        for (int t4 = 0; t4 < 4; t4++) {
            #pragma unroll
            for (int i = 0; i < 2; i++) {
                int idx = tid + 256 * i;
                int r = idx >> 2, c = idx & 3;
                uint32_t dst = bufb + t4*TILE_B + (uint32_t)(r*(ROWPAD*2) + c*16);
                cp_async16(dst, srcs[t4] + (size_t)r * CC + c*8);
            }
        }
        cp_commit();
    }

    for (int kt = 0; kt < NT; kt++) {
        const uint32_t cur = sb + (kt & 1) * BUF_B;
        if (kt < NT - 1) {
            const uint32_t nxtb = sb + ((kt + 1) & 1) * BUF_B;
            const int k0 = (kt + 1) * GBK;
            #pragma unroll
            for (int t4 = 0; t4 < 4; t4++) {
                #pragma unroll
                for (int i = 0; i < 2; i++) {
                    int idx = tid + 256 * i;
                    int r = idx >> 2, c = idx & 3;
                    uint32_t dst = nxtb + t4*TILE_B + (uint32_t)(r*(ROWPAD*2) + c*16);
                    cp_async16(dst, srcs[t4] + (size_t)r * CC + k0 + c*8);
                }
            }
            cp_commit();
            cp_wait1();
        } else {
            cp_wait0();
        }
        __syncthreads();

        #pragma unroll
        for (int k16 = 0; k16 < 2; k16++) {
            const uint32_t ko = (uint32_t)(k16 * 32);
            uint32_t ah[4][4], al[4][4], bh[2][4], bl[2][4];
            #pragma unroll
            for (int mt = 0; mt < 4; mt++) {
                ldsm4(ah[mt], cur + 0*TILE_B + aRow + (uint32_t)(mt*16*(ROWPAD*2)) + ko);
                ldsm4(al[mt], cur + 1*TILE_B + aRow + (uint32_t)(mt*16*(ROWPAD*2)) + ko);
            }
            #pragma unroll
            for (int nt = 0; nt < 2; nt++) {
                ldsm4(bh[nt], cur + 2*TILE_B + bRow + (uint32_t)(nt*16*(ROWPAD*2)) + ko);
                ldsm4(bl[nt], cur + 3*TILE_B + bRow + (uint32_t)(nt*16*(ROWPAD*2)) + ko);
            }
            #pragma unroll
            for (int mt = 0; mt < 4; mt++) {
                #pragma unroll
                for (int nt = 0; nt < 4; nt++) {
                    const uint32_t* bhp = &bh[nt >> 1][(nt & 1) * 2];
                    const uint32_t* blp = &bl[nt >> 1][(nt & 1) * 2];
                    mma16816(acc[mt][nt], ah[mt], bhp);
                    mma16816(acc[mt][nt], ah[mt], blp);
                    mma16816(acc[mt][nt], al[mt], bhp);
                }
            }
        }
        __syncthreads();
    }

    // ---- YAT epilogue from registers ----
    const float scale = powf(sqrtf((float)N) / log1pf((float)N), alpha[0]);
    const int mbase = m0 + wr*64 + (lane >> 2);
    const int nbase = n0 + wc*32 + (lane & 3)*2;

    #pragma unroll
    for (int mt = 0; mt < 4; mt++) {
        #pragma unroll
        for (int half = 0; half < 2; half++) {
            const int gm = mbase + mt*16 + half*8;
            const float x2v = x2[gm];
            const int bb = gm >> 10, t = gm & 1023;
            #pragma unroll
            for (int nt = 0; nt < 4; nt++) {
                float y0 = acc[mt][nt][half*2 + 0];
                float y1 = acc[mt][nt][half*2 + 1];
                const int gn = nbase + nt*8;
                float k20 = k2[gn], k21 = k2[gn+1];
                float b0 = bias[gn], b1 = bias[gn+1];
                float v0 = (y0*y0) / (x2v + k20 - 2.f*y0 + EPS_C) * scale + b0;
                float v1 = (y1*y1) / (x2v + k21 - 2.f*y1 + EPS_C) * scale + b1;
                if (mode == 0) {
                    #pragma unroll
                    for (int e = 0; e < 2; e++) {
                        int g = gn + e;
                        float val = e ? v1 : v0;
                        int s = g >> 10;
                        int hh = (g & 1023) >> 6;
                        int dd = g & 63;
                        size_t idx = (((size_t)(bb * NHEADS_EFF + dd) * TT) + t) * HD_EFF + hh;
                        if (s == 0) g_q[idx] = val;
                        else if (s == 1) g_k[idx] = val;
                        else g_v[idx] = val;
                    }
                } else {
                    float2 o; o.x = v0; o.y = v1;
                    *(float2*)(outP + (size_t)gm * N + gn) = o;
                }
            }
        }
    }
}

// ---------------- attention (unchanged) ----------------
#define AJT 128
__global__ __launch_bounds__(256)
void attn_kernel(const float* __restrict__ alpha_attn) {
    __shared__ float Kt[AJT * 16];
    __shared__ float Vt[AJT * 16];
    __shared__ float K2t[AJT];

    const int tid = threadIdx.x;
    const int lane = tid & 31;
    const int w = tid >> 5;
    const int chunk = blockIdx.x;
    const int d = blockIdx.y;
    const int b = blockIdx.z;
    const int i = chunk * 256 + w * 32 + lane;

    const float inv_scale = powf(64.0f / log1pf(64.0f), alpha_attn[0]);
    const size_t hb = (size_t)(b * NHEADS_EFF + d) * TT * HD_EFF;

    u64 qq[8];
    {
        const ulonglong2* qp = (const ulonglong2*)(g_q + hb + (size_t)i * 16);
        #pragma unroll
        for (int e = 0; e < 4; e++) {
            ulonglong2 u = qp[e];
            qq[e * 2] = u.x; qq[e * 2 + 1] = u.y;
        }
    }
    float q2;
    {
        u64 s2 = 0ull;
        #pragma unroll
        for (int e = 0; e < 8; e++) s2 = ffma2(qq[e], qq[e], s2);
        float lo, hi; upk2(s2, lo, hi);
        q2 = lo + hi + EPS_C;
    }

    u64 acc[8];
    #pragma unroll
    for (int e = 0; e < 8; e++) acc[e] = 0ull;
    float l = 0.f;

    const int n_st = 2 * chunk + 2;
    for (int st = 0; st < n_st; st++) {
        __syncthreads();
        {
            const float4* ks = (const float4*)(g_k + hb + (size_t)st * AJT * 16);
            const float4* vs = (const float4*)(g_v + hb + (size_t)st * AJT * 16);
            ((float4*)Kt)[tid]       = ks[tid];
            ((float4*)Kt)[tid + 256] = ks[tid + 256];
            ((float4*)Vt)[tid]       = vs[tid];
            ((float4*)Vt)[tid + 256] = vs[tid + 256];
            if (tid < AJT) K2t[tid] = g_kk[(size_t)(b * NHEADS_EFF + d) * TT + st * AJT + tid];
        }
        __syncthreads();

        int lim = chunk * 256 + w * 32 + 32 - st * AJT;
        if (lim > AJT) lim = AJT;
        const int jb = st * AJT;
        #pragma unroll 2
        for (int jj = 0; jj < lim; jj++) {
            const u64* kp = (const u64*)&Kt[jj * 16];
            u64 s2 = 0ull;
            #pragma unroll
            for (int e = 0; e < 8; e++) s2 = ffma2(qq[e], kp[e], s2);
            float lo, hi; upk2(s2, lo, hi);
            float s = lo + hi;
            float den = fmaf(-2.f, s, q2 + K2t[jj]);
            float a = __fdividef(s * s * inv_scale, den);
            float p = __expf(a);
            if (jb + jj > i) p = 0.f;
            l += p;
            u64 pp = pk2(p, p);
            const u64* vp = (const u64*)&Vt[jj * 16];
            #pragma unroll
            for (int e = 0; e < 8; e++) acc[e] = ffma2(pp, vp[e], acc[e]);
        }
    }

    float invl = 1.0f / l;
    u64 iv = pk2(invl, invl);
    ulonglong2* outp = (ulonglong2*)(&g_att[((size_t)(b * TT + i)) * CC + d * 16]);
    #pragma unroll
    for (int e = 0; e < 4; e++) {
        ulonglong2 u;
        u.x = fmul2(acc[e * 2], iv);
        u.y = fmul2(acc[e * 2 + 1], iv);
        outp[e] = u;
    }
}

// ---------------- launch ----------------
extern "C" void kernel_launch(void* const* d_in, const int* in_sizes, int n_in,
                              void* d_out, int out_size) {
    const float* x          = (const float*)d_in[0];
    const float* w_qkv      = (const float*)d_in[2];
    const float* b_qkv      = (const float*)d_in[3];
    const float* alpha_qkv  = (const float*)d_in[4];
    const float* w_proj     = (const float*)d_in[5];
    const float* b_proj     = (const float*)d_in[6];
    const float* alpha_proj = (const float*)d_in[7];
    const float* alpha_attn = (const float*)d_in[8];
    float* out = (float*)d_out;

    void *p_att, *p_x2a, *p_x2b, *p_k2a, *p_k2b;
    void *p_ahi, *p_alo, *p_bqhi, *p_bqlo, *p_bphi, *p_bplo;
    cudaGetSymbolAddress(&p_att,  g_att);
    cudaGetSymbolAddress(&p_x2a,  g_x2a);
    cudaGetSymbolAddress(&p_x2b,  g_x2b);
    cudaGetSymbolAddress(&p_k2a,  g_k2a);
    cudaGetSymbolAddress(&p_k2b,  g_k2b);
    cudaGetSymbolAddress(&p_ahi,  g_ahi);
    cudaGetSymbolAddress(&p_alo,  g_alo);
    cudaGetSymbolAddress(&p_bqhi, g_bqhi);
    cudaGetSymbolAddress(&p_bqlo, g_bqlo);
    cudaGetSymbolAddress(&p_bphi, g_bphi);
    cudaGetSymbolAddress(&p_bplo, g_bplo);

    cudaFuncSetAttribute(gemm_mma_kernel, cudaFuncAttributeMaxDynamicSharedMemorySize, GDYN);

    rownorm_kernel<<<MROWS, 256>>>(x, (float*)p_x2a);
    colnorm_kernel<<<F_QKV / 256, 256>>>(w_qkv, F_QKV, (float*)p_k2a);
    colnorm_kernel<<<CC / 256, 256>>>(w_proj, CC, (float*)p_k2b);
    split_kernel<<<MROWS * CC / 256, 256>>>(x, (__nv_bfloat16*)p_ahi, (__nv_bfloat16*)p_alo);
    {
        dim3 g(F_QKV / 32, CC / 32);
        tsplit_kernel<<<g, 256>>>(w_qkv, F_QKV, (__nv_bfloat16*)p_bqhi, (__nv_bfloat16*)p_bqlo);
    }
    {
        dim3 g(CC / 32, CC / 32);
        tsplit_kernel<<<g, 256>>>(w_proj, CC, (__nv_bfloat16*)p_bphi, (__nv_bfloat16*)p_bplo);
    }

    {
        dim3 grid(F_QKV / 128, MROWS / 128);
        gemm_mma_kernel<<<grid, 256, GDYN>>>(
            (const __nv_bfloat16*)p_ahi, (const __nv_bfloat16*)p_alo,
            (const __nv_bfloat16*)p_bqhi, (const __nv_bfloat16*)p_bqlo,
            (const float*)p_x2a, (const float*)p_k2a, b_qkv, alpha_qkv,
            F_QKV, 0, nullptr);
    }

    kk_kernel<<<(BATCH * NHEADS_EFF * TT) / 256, 256>>>();

    {
        dim3 grid(TT / 256, NHEADS_EFF, BATCH);
        attn_kernel<<<grid, 256>>>(alpha_attn);
    }

    rownorm_kernel<<<MROWS, 256>>>((const float*)p_att, (float*)p_x2b);
    split_kernel<<<MROWS * CC / 256, 256>>>((const float*)p_att,
                                            (__nv_bfloat16*)p_ahi, (__nv_bfloat16*)p_alo);
    {
        dim3 grid(CC / 128, MROWS / 128);
        gemm_mma_kernel<<<grid, 256, GDYN>>>(
            (const __nv_bfloat16*)p_ahi, (const __nv_bfloat16*)p_alo,
            (const __nv_bfloat16*)p_bphi, (const __nv_bfloat16*)p_bplo,
            (const float*)p_x2b, (const float*)p_k2b, b_proj, alpha_proj,
            CC, 1, out);
    }
}

// round 5
// speedup vs baseline: 2.0481x; 1.2051x over previous
#include <cuda_runtime.h>
#include <cuda_bf16.h>
#include <math.h>
#include <stdint.h>

#define EPS_C (1.0f/137.0f)

#define BATCH 2
#define TT 1024
#define CC 1024
#define F_QKV 3072
#define MROWS (BATCH*TT)
#define NHEADS_EFF 64
#define HD_EFF 16

typedef unsigned long long u64;

// ---------------- scratch ----------------
__device__ float g_q[BATCH*NHEADS_EFF*TT*HD_EFF];
__device__ float g_k[BATCH*NHEADS_EFF*TT*HD_EFF];
__device__ float g_v[BATCH*NHEADS_EFF*TT*HD_EFF];
__device__ float g_att[MROWS*CC];
__device__ float g_x2a[MROWS];
__device__ float g_x2b[MROWS];
__device__ float g_k2a[F_QKV];
__device__ float g_k2b[CC];
__device__ float g_kk[BATCH*NHEADS_EFF*TT];
__device__ float g_qq[BATCH*NHEADS_EFF*TT];

__device__ __nv_bfloat16 g_ahi[MROWS*CC];
__device__ __nv_bfloat16 g_alo[MROWS*CC];
__device__ __nv_bfloat16 g_bqhi[F_QKV*CC];
__device__ __nv_bfloat16 g_bqlo[F_QKV*CC];
__device__ __nv_bfloat16 g_bphi[CC*CC];
__device__ __nv_bfloat16 g_bplo[CC*CC];

// attention operand splits
__device__ __nv_bfloat16 g_qhi[BATCH*NHEADS_EFF*TT*HD_EFF];
__device__ __nv_bfloat16 g_qlo[BATCH*NHEADS_EFF*TT*HD_EFF];
__device__ __nv_bfloat16 g_khi[BATCH*NHEADS_EFF*TT*HD_EFF];
__device__ __nv_bfloat16 g_klo[BATCH*NHEADS_EFF*TT*HD_EFF];
__device__ __nv_bfloat16 g_vthi[BATCH*NHEADS_EFF*HD_EFF*TT];  // [b,d,hd,t]
__device__ __nv_bfloat16 g_vtlo[BATCH*NHEADS_EFF*HD_EFF*TT];

// ---------------- helpers ----------------
__device__ __forceinline__ unsigned smem_u32(const void* p) {
    return (unsigned)__cvta_generic_to_shared(p);
}
__device__ __forceinline__ void cp_async16(unsigned dst, const void* src) {
    asm volatile("cp.async.cg.shared.global [%0], [%1], 16;" :: "r"(dst), "l"(src));
}
__device__ __forceinline__ void cp_commit() { asm volatile("cp.async.commit_group;"); }
__device__ __forceinline__ void cp_wait0()  { asm volatile("cp.async.wait_group 0;"); }
__device__ __forceinline__ void cp_wait1()  { asm volatile("cp.async.wait_group 1;"); }

__device__ __forceinline__ void ldsm4(uint32_t* r, uint32_t addr) {
    asm volatile("ldmatrix.sync.aligned.m8n8.x4.shared.b16 {%0,%1,%2,%3},[%4];"
        : "=r"(r[0]), "=r"(r[1]), "=r"(r[2]), "=r"(r[3]) : "r"(addr));
}
__device__ __forceinline__ void mma16816(float* c, const uint32_t* a, const uint32_t* b) {
    asm volatile("mma.sync.aligned.m16n8k16.row.col.f32.bf16.bf16.f32 "
        "{%0,%1,%2,%3},{%4,%5,%6,%7},{%8,%9},{%0,%1,%2,%3};"
        : "+f"(c[0]), "+f"(c[1]), "+f"(c[2]), "+f"(c[3])
        : "r"(a[0]), "r"(a[1]), "r"(a[2]), "r"(a[3]), "r"(b[0]), "r"(b[1]));
}
// pack {lo,hi} floats -> bf16x2 reg
__device__ __forceinline__ uint32_t pkbf(float lo, float hi) {
    uint32_t r; asm("cvt.rn.bf16x2.f32 %0,%1,%2;" : "=r"(r) : "f"(hi), "f"(lo)); return r;
}
__device__ __forceinline__ float2 ubf(uint32_t u) {
    __nv_bfloat162 h = *reinterpret_cast<__nv_bfloat162*>(&u);
    return __bfloat1622float2(h);
}

// ---------------- row norms ----------------
__global__ void rownorm_kernel(const float* __restrict__ src, float* __restrict__ dst) {
    int row = blockIdx.x;
    const float* base = src + (size_t)row * CC;
    float s = 0.f;
    for (int c = threadIdx.x; c < CC; c += 256) {
        float v = base[c];
        s = fmaf(v, v, s);
    }
    #pragma unroll
    for (int off = 16; off; off >>= 1) s += __shfl_xor_sync(~0u, s, off);
    __shared__ float red[8];
    if ((threadIdx.x & 31) == 0) red[threadIdx.x >> 5] = s;
    __syncthreads();
    if (threadIdx.x == 0) {
        float t = 0.f;
        #pragma unroll
        for (int i = 0; i < 8; i++) t += red[i];
        dst[row] = t;
    }
}

// ---------------- col norms ----------------
__global__ void colnorm_kernel(const float* __restrict__ w, int N, float* __restrict__ dst) {
    int f = blockIdx.x * 256 + threadIdx.x;
    if (f >= N) return;
    float s = 0.f;
    #pragma unroll 8
    for (int c = 0; c < CC; c++) {
        float v = w[(size_t)c * N + f];
        s = fmaf(v, v, s);
    }
    dst[f] = s;
}

// ---------------- bf16 split (element-wise, A operand) ----------------
__global__ void split_kernel(const float* __restrict__ src,
                             __nv_bfloat16* __restrict__ hi, __nv_bfloat16* __restrict__ lo) {
    int i = blockIdx.x * 256 + threadIdx.x;
    float v = src[i];
    __nv_bfloat16 h = __float2bfloat16(v);
    float r = v - __bfloat162float(h);
    hi[i] = h;
    lo[i] = __float2bfloat16(r);
}

// ---------------- bf16 split + transpose: w[K,N] -> hiT/loT [N,K] ----------------
__global__ void tsplit_kernel(const float* __restrict__ w, int N,
                              __nv_bfloat16* __restrict__ hiT, __nv_bfloat16* __restrict__ loT) {
    __shared__ float tile[32][33];
    int n0 = blockIdx.x * 32, k0 = blockIdx.y * 32;
    int tx = threadIdx.x & 31, ty = threadIdx.x >> 5;
    #pragma unroll
    for (int r = 0; r < 32; r += 8)
        tile[ty + r][tx] = w[(size_t)(k0 + ty + r) * N + n0 + tx];
    __syncthreads();
    #pragma unroll
    for (int r = 0; r < 32; r += 8) {
        float v = tile[tx][ty + r];
        __nv_bfloat16 h = __float2bfloat16(v);
        float res = v - __bfloat162float(h);
        size_t idx = (size_t)(n0 + ty + r) * CC + k0 + tx;
        hiT[idx] = h;
        loT[idx] = __float2bfloat16(res);
    }
}

// ---------------- per-16-row norms (attention q2/k2) ----------------
__global__ void norm16_kernel(const float* __restrict__ src, float* __restrict__ dst) {
    int r = blockIdx.x * 256 + threadIdx.x;
    const float4* p = (const float4*)(src + (size_t)r * 16);
    float4 a = p[0], b = p[1], c = p[2], d = p[3];
    float s = a.x*a.x + a.y*a.y + a.z*a.z + a.w*a.w
            + b.x*b.x + b.y*b.y + b.z*b.z + b.w*b.w
            + c.x*c.x + c.y*c.y + c.z*c.z + c.w*c.w
            + d.x*d.x + d.y*d.y + d.z*d.z + d.w*d.w;
    dst[r] = s;
}

// ---------------- q/k bf16 split ----------------
__global__ void qksplit_kernel() {
    size_t i4 = ((size_t)blockIdx.x * 256 + threadIdx.x) * 4;
    float4 q = *(const float4*)&g_q[i4];
    float4 k = *(const float4*)&g_k[i4];
    uint2 qh, ql, kh, kl;
    __nv_bfloat16 h;
    float r0, r1;
    h = __float2bfloat16(q.x); r0 = q.x - __bfloat162float(h);
    h = __float2bfloat16(q.y); r1 = q.y - __bfloat162float(h);
    qh.x = pkbf(q.x, q.y); ql.x = pkbf(r0, r1);
    h = __float2bfloat16(q.z); r0 = q.z - __bfloat162float(h);
    h = __float2bfloat16(q.w); r1 = q.w - __bfloat162float(h);
    qh.y = pkbf(q.z, q.w); ql.y = pkbf(r0, r1);
    h = __float2bfloat16(k.x); r0 = k.x - __bfloat162float(h);
    h = __float2bfloat16(k.y); r1 = k.y - __bfloat162float(h);
    kh.x = pkbf(k.x, k.y); kl.x = pkbf(r0, r1);
    h = __float2bfloat16(k.z); r0 = k.z - __bfloat162float(h);
    h = __float2bfloat16(k.w); r1 = k.w - __bfloat162float(h);
    kh.y = pkbf(k.z, k.w); kl.y = pkbf(r0, r1);
    *(uint2*)&g_qhi[i4] = qh;
    *(uint2*)&g_qlo[i4] = ql;
    *(uint2*)&g_khi[i4] = kh;
    *(uint2*)&g_klo[i4] = kl;
}

// ---------------- v transpose + split: [t,hd] -> [hd,t] ----------------
__global__ void vtsplit_kernel() {
    __shared__ float ts[16][132];
    const int tid = threadIdx.x;
    const int t0 = blockIdx.x * 128;
    const size_t hb = (size_t)(blockIdx.z * NHEADS_EFF + blockIdx.y) * TT * HD_EFF;
    const float* src = g_v + hb + (size_t)t0 * 16;
    {
        int t = tid >> 1, h0 = (tid & 1) * 8;
        float4 v0 = *(const float4*)&src[t * 16 + h0];
        float4 v1 = *(const float4*)&src[t * 16 + h0 + 4];
        ts[h0 + 0][t] = v0.x; ts[h0 + 1][t] = v0.y; ts[h0 + 2][t] = v0.z; ts[h0 + 3][t] = v0.w;
        ts[h0 + 4][t] = v1.x; ts[h0 + 5][t] = v1.y; ts[h0 + 6][t] = v1.z; ts[h0 + 7][t] = v1.w;
    }
    __syncthreads();
    int h = tid >> 4, c = (tid & 15) * 8;
    uint4 hiv, lov;
    uint32_t* hp = (uint32_t*)&hiv;
    uint32_t* lp = (uint32_t*)&lov;
    #pragma unroll
    for (int e = 0; e < 4; e++) {
        float x = ts[h][c + 2 * e], y = ts[h][c + 2 * e + 1];
        __nv_bfloat16 hx = __float2bfloat16(x), hy = __float2bfloat16(y);
        hp[e] = pkbf(x, y);
        lp[e] = pkbf(x - __bfloat162float(hx), y - __bfloat162float(hy));
    }
    size_t dst = hb + (size_t)h * TT + t0 + c;
    *(uint4*)&g_vthi[dst] = hiv;
    *(uint4*)&g_vtlo[dst] = lov;
}

// ---------------- mma.sync GEMM + YAT epilogue (unchanged from R4) ----------------
#define GBK 32
#define ROWPAD 40
#define TILE_B (128*ROWPAD*2)
#define BUF_B  (4*TILE_B)
#define GDYN   (2*BUF_B)

__global__ __launch_bounds__(256, 1)
void gemm_mma_kernel(const __nv_bfloat16* __restrict__ Ahi, const __nv_bfloat16* __restrict__ Alo,
                     const __nv_bfloat16* __restrict__ BhiT, const __nv_bfloat16* __restrict__ BloT,
                     const float* __restrict__ x2, const float* __restrict__ k2,
                     const float* __restrict__ bias, const float* __restrict__ alpha,
                     int N, int mode, float* __restrict__ outP) {
    extern __shared__ char smem[];
    const uint32_t sb = smem_u32(smem);
    const int tid = threadIdx.x;
    const int wid = tid >> 5, lane = tid & 31;
    const int wr = wid >> 2, wc = wid & 3;
    const int m0 = blockIdx.y * 128, n0 = blockIdx.x * 128;

    const __nv_bfloat16* srcs[4] = {
        Ahi + (size_t)m0 * CC, Alo + (size_t)m0 * CC,
        BhiT + (size_t)n0 * CC, BloT + (size_t)n0 * CC };

    float acc[4][4][4];
    #pragma unroll
    for (int i = 0; i < 4; i++)
        #pragma unroll
        for (int j = 0; j < 4; j++)
            #pragma unroll
            for (int e = 0; e < 4; e++) acc[i][j][e] = 0.f;

    const int grp = lane >> 3;
    const uint32_t aRow = (uint32_t)((wr*64 + (grp&1)*8 + (lane&7)) * (ROWPAD*2) + (grp>>1)*16);
    const uint32_t bRow = (uint32_t)((wc*32 + (grp>>1)*8 + (lane&7)) * (ROWPAD*2) + (grp&1)*16);

    const int NT = CC / GBK;

    {
        const uint32_t bufb = sb;
        #pragma unroll
        for (int t4 = 0; t4 < 4; t4++) {
            #pragma unroll
            for (int i = 0; i < 2; i++) {
                int idx = tid + 256 * i;
                int r = idx >> 2, c = idx & 3;
                uint32_t dst = bufb + t4*TILE_B + (uint32_t)(r*(ROWPAD*2) + c*16);
                cp_async16(dst, srcs[t4] + (size_t)r * CC + c*8);
            }
        }
        cp_commit();
    }

    for (int kt = 0; kt < NT; kt++) {
        const uint32_t cur = sb + (kt & 1) * BUF_B;
        if (kt < NT - 1) {
            const uint32_t nxtb = sb + ((kt + 1) & 1) * BUF_B;
            const int k0 = (kt + 1) * GBK;
            #pragma unroll
            for (int t4 = 0; t4 < 4; t4++) {
                #pragma unroll
                for (int i = 0; i < 2; i++) {
                    int idx = tid + 256 * i;
                    int r = idx >> 2, c = idx & 3;
                    uint32_t dst = nxtb + t4*TILE_B + (uint32_t)(r*(ROWPAD*2) + c*16);
                    cp_async16(dst, srcs[t4] + (size_t)r * CC + k0 + c*8);
                }
            }
            cp_commit();
            cp_wait1();
        } else {
            cp_wait0();
        }
        __syncthreads();

        #pragma unroll
        for (int k16 = 0; k16 < 2; k16++) {
            const uint32_t ko = (uint32_t)(k16 * 32);
            uint32_t ah[4][4], al[4][4], bh[2][4], bl[2][4];
            #pragma unroll
            for (int mt = 0; mt < 4; mt++) {
                ldsm4(ah[mt], cur + 0*TILE_B + aRow + (uint32_t)(mt*16*(ROWPAD*2)) + ko);
                ldsm4(al[mt], cur + 1*TILE_B + aRow + (uint32_t)(mt*16*(ROWPAD*2)) + ko);
            }
            #pragma unroll
            for (int nt = 0; nt < 2; nt++) {
                ldsm4(bh[nt], cur + 2*TILE_B + bRow + (uint32_t)(nt*16*(ROWPAD*2)) + ko);
                ldsm4(bl[nt], cur + 3*TILE_B + bRow + (uint32_t)(nt*16*(ROWPAD*2)) + ko);
            }
            #pragma unroll
            for (int mt = 0; mt < 4; mt++) {
                #pragma unroll
                for (int nt = 0; nt < 4; nt++) {
                    const uint32_t* bhp = &bh[nt >> 1][(nt & 1) * 2];
                    const uint32_t* blp = &bl[nt >> 1][(nt & 1) * 2];
                    mma16816(acc[mt][nt], ah[mt], bhp);
                    mma16816(acc[mt][nt], ah[mt], blp);
                    mma16816(acc[mt][nt], al[mt], bhp);
                }
            }
        }
        __syncthreads();
    }

    const float scale = powf(sqrtf((float)N) / log1pf((float)N), alpha[0]);
    const int mbase = m0 + wr*64 + (lane >> 2);
    const int nbase = n0 + wc*32 + (lane & 3)*2;

    #pragma unroll
    for (int mt = 0; mt < 4; mt++) {
        #pragma unroll
        for (int half = 0; half < 2; half++) {
            const int gm = mbase + mt*16 + half*8;
            const float x2v = x2[gm];
            const int bb = gm >> 10, t = gm & 1023;
            #pragma unroll
            for (int nt = 0; nt < 4; nt++) {
                float y0 = acc[mt][nt][half*2 + 0];
                float y1 = acc[mt][nt][half*2 + 1];
                const int gn = nbase + nt*8;
                float k20 = k2[gn], k21 = k2[gn+1];
                float b0 = bias[gn], b1 = bias[gn+1];
                float v0 = (y0*y0) / (x2v + k20 - 2.f*y0 + EPS_C) * scale + b0;
                float v1 = (y1*y1) / (x2v + k21 - 2.f*y1 + EPS_C) * scale + b1;
                if (mode == 0) {
                    #pragma unroll
                    for (int e = 0; e < 2; e++) {
                        int g = gn + e;
                        float val = e ? v1 : v0;
                        int s = g >> 10;
                        int hh = (g & 1023) >> 6;
                        int dd = g & 63;
                        size_t idx = (((size_t)(bb * NHEADS_EFF + dd) * TT) + t) * HD_EFF + hh;
                        if (s == 0) g_q[idx] = val;
                        else if (s == 1) g_k[idx] = val;
                        else g_v[idx] = val;
                    }
                } else {
                    float2 o; o.x = v0; o.y = v1;
                    *(float2*)(outP + (size_t)gm * N + gn) = o;
                }
            }
        }
    }
}

// ---------------- tensor-core attention ----------------
// block: 128 q-rows of one (b,d) head; 8 warps x 16 rows; j-tiles of 128 (causal)
__global__ __launch_bounds__(256, 1)
void attn_mma_kernel(const float* __restrict__ alpha_attn) {
    __shared__ __nv_bfloat16 Kh[128*24];
    __shared__ __nv_bfloat16 Kl[128*24];
    __shared__ __nv_bfloat16 VTh[16*136];
    __shared__ __nv_bfloat16 VTl[16*136];
    __shared__ float k2s[128];

    const int tid = threadIdx.x, lane = tid & 31, wr = tid >> 5;
    const int g = lane >> 2, tc = lane & 3;
    const int itile = blockIdx.x, dh = blockIdx.y, b = blockIdx.z;
    const int i0 = itile * 128;
    const size_t hb = (size_t)(b * NHEADS_EFF + dh) * TT * HD_EFF;
    const size_t nb = (size_t)(b * NHEADS_EFF + dh) * TT;

    const float inv_scale = powf(64.0f / log1pf(64.0f), alpha_attn[0]);

    const int r0 = i0 + wr * 16 + g;

    uint32_t aq_h[4], aq_l[4];
    {
        const __nv_bfloat16* qh = g_qhi + hb;
        const __nv_bfloat16* ql = g_qlo + hb;
        aq_h[0] = *(const uint32_t*)&qh[(size_t)r0 * 16 + 2*tc];
        aq_h[1] = *(const uint32_t*)&qh[(size_t)(r0+8) * 16 + 2*tc];
        aq_h[2] = *(const uint32_t*)&qh[(size_t)r0 * 16 + 8 + 2*tc];
        aq_h[3] = *(const uint32_t*)&qh[(size_t)(r0+8) * 16 + 8 + 2*tc];
        aq_l[0] = *(const uint32_t*)&ql[(size_t)r0 * 16 + 2*tc];
        aq_l[1] = *(const uint32_t*)&ql[(size_t)(r0+8) * 16 + 2*tc];
        aq_l[2] = *(const uint32_t*)&ql[(size_t)r0 * 16 + 8 + 2*tc];
        aq_l[3] = *(const uint32_t*)&ql[(size_t)(r0+8) * 16 + 8 + 2*tc];
    }
    const float q20 = g_qq[nb + r0] + EPS_C;
    const float q21 = g_qq[nb + r0 + 8] + EPS_C;

    float O0[8];
    #pragma unroll
    for (int e = 0; e < 8; e++) O0[e] = 0.f;
    float l0 = 0.f, l1 = 0.f;

    for (int jt = 0; jt <= itile; jt++) {
        const int j0 = jt * 128;
        __syncthreads();
        {
            int row = tid >> 1, hcol = (tid & 1) * 8;
            *(uint4*)&Kh[row*24 + hcol] = *(const uint4*)&g_khi[hb + (size_t)(j0 + row)*16 + hcol];
            *(uint4*)&Kl[row*24 + hcol] = *(const uint4*)&g_klo[hb + (size_t)(j0 + row)*16 + hcol];
            int vrow = tid >> 4, vcol = (tid & 15) * 8;
            *(uint4*)&VTh[vrow*136 + vcol] = *(const uint4*)&g_vthi[hb + (size_t)vrow*TT + j0 + vcol];
            *(uint4*)&VTl[vrow*136 + vcol] = *(const uint4*)&g_vtlo[hb + (size_t)vrow*TT + j0 + vcol];
            if (tid < 128) k2s[tid] = g_kk[nb + j0 + tid];
        }
        __syncthreads();

        // S = Q K^T (128x128 per block; this warp: 16 rows x 128 cols)
        float S[16][4];
        #pragma unroll
        for (int nt = 0; nt < 16; nt++) {
            uint32_t bh[2], bl[2];
            int kr = (nt*8 + g) * 24 + 2*tc;
            bh[0] = *(const uint32_t*)&Kh[kr];
            bh[1] = *(const uint32_t*)&Kh[kr + 8];
            bl[0] = *(const uint32_t*)&Kl[kr];
            bl[1] = *(const uint32_t*)&Kl[kr + 8];
            S[nt][0] = S[nt][1] = S[nt][2] = S[nt][3] = 0.f;
            mma16816(S[nt], aq_h, bh);
            mma16816(S[nt], aq_h, bl);
            mma16816(S[nt], aq_l, bh);
        }

        // YAT softmax weights (no-max exp; scores tiny & >= 0)
        const bool maskt = (jt == itile);
        #pragma unroll
        for (int nt = 0; nt < 16; nt++) {
            #pragma unroll
            for (int c = 0; c < 4; c++) {
                float s = S[nt][c];
                float k2v = k2s[nt*8 + 2*tc + (c & 1)];
                float q2v = (c < 2) ? q20 : q21;
                float den = fmaf(-2.f, s, q2v + k2v);
                float p = __expf(__fdividef(s * s * inv_scale, den));
                if (maskt) {
                    int j = j0 + nt*8 + 2*tc + (c & 1);
                    int iq = (c < 2) ? r0 : r0 + 8;
                    if (j > iq) p = 0.f;
                }
                if (c < 2) l0 += p; else l1 += p;
                S[nt][c] = p;
            }
        }

        // O += P V  (split P to preserve precision)
        #pragma unroll
        for (int kb = 0; kb < 8; kb++) {
            float* Sa = S[2*kb];
            float* Sb = S[2*kb + 1];
            uint32_t ph[4], pl[4];
            ph[0] = pkbf(Sa[0], Sa[1]);
            ph[1] = pkbf(Sa[2], Sa[3]);
            ph[2] = pkbf(Sb[0], Sb[1]);
            ph[3] = pkbf(Sb[2], Sb[3]);
            float2 f;
            f = ubf(ph[0]); pl[0] = pkbf(Sa[0] - f.x, Sa[1] - f.y);
            f = ubf(ph[1]); pl[1] = pkbf(Sa[2] - f.x, Sa[3] - f.y);
            f = ubf(ph[2]); pl[2] = pkbf(Sb[0] - f.x, Sb[1] - f.y);
            f = ubf(ph[3]); pl[3] = pkbf(Sb[2] - f.x, Sb[3] - f.y);
            #pragma unroll
            for (int dt = 0; dt < 2; dt++) {
                uint32_t bvh[2], bvl[2];
                int vr = (dt*8 + g) * 136 + kb*16 + 2*tc;
                bvh[0] = *(const uint32_t*)&VTh[vr];
                bvh[1] = *(const uint32_t*)&VTh[vr + 8];
                bvl[0] = *(const uint32_t*)&VTl[vr];
                bvl[1] = *(const uint32_t*)&VTl[vr + 8];
                float* Od = &O0[dt*4];
                mma16816(Od, ph, bvh);
                mma16816(Od, ph, bvl);
                mma16816(Od, pl, bvh);
            }
        }
    }

    // reduce row-sums across the quad (lanes sharing a row)
    l0 += __shfl_xor_sync(~0u, l0, 1); l0 += __shfl_xor_sync(~0u, l0, 2);
    l1 += __shfl_xor_sync(~0u, l1, 1); l1 += __shfl_xor_sync(~0u, l1, 2);
    const float inv0 = 1.f / l0, inv1 = 1.f / l1;

    float* ob0 = g_att + (size_t)(b*TT + r0) * CC + dh*16;
    float* ob1 = g_att + (size_t)(b*TT + r0 + 8) * CC + dh*16;
    #pragma unroll
    for (int dt = 0; dt < 2; dt++) {
        int col = dt*8 + 2*tc;
        float2 o0; o0.x = O0[dt*4+0]*inv0; o0.y = O0[dt*4+1]*inv0;
        float2 o1; o1.x = O0[dt*4+2]*inv1; o1.y = O0[dt*4+3]*inv1;
        *(float2*)&ob0[col] = o0;
        *(float2*)&ob1[col] = o1;
    }
}

// ---------------- launch ----------------
extern "C" void kernel_launch(void* const* d_in, const int* in_sizes, int n_in,
                              void* d_out, int out_size) {
    const float* x          = (const float*)d_in[0];
    const float* w_qkv      = (const float*)d_in[2];
    const float* b_qkv      = (const float*)d_in[3];
    const float* alpha_qkv  = (const float*)d_in[4];
    const float* w_proj     = (const float*)d_in[5];
    const float* b_proj     = (const float*)d_in[6];
    const float* alpha_proj = (const float*)d_in[7];
    const float* alpha_attn = (const float*)d_in[8];
    float* out = (float*)d_out;

    void *p_att, *p_x2a, *p_x2b, *p_k2a, *p_k2b, *p_q, *p_k, *p_qq, *p_kk;
    void *p_ahi, *p_alo, *p_bqhi, *p_bqlo, *p_bphi, *p_bplo;
    cudaGetSymbolAddress(&p_att,  g_att);
    cudaGetSymbolAddress(&p_x2a,  g_x2a);
    cudaGetSymbolAddress(&p_x2b,  g_x2b);
    cudaGetSymbolAddress(&p_k2a,  g_k2a);
    cudaGetSymbolAddress(&p_k2b,  g_k2b);
    cudaGetSymbolAddress(&p_q,    g_q);
    cudaGetSymbolAddress(&p_k,    g_k);
    cudaGetSymbolAddress(&p_qq,   g_qq);
    cudaGetSymbolAddress(&p_kk,   g_kk);
    cudaGetSymbolAddress(&p_ahi,  g_ahi);
    cudaGetSymbolAddress(&p_alo,  g_alo);
    cudaGetSymbolAddress(&p_bqhi, g_bqhi);
    cudaGetSymbolAddress(&p_bqlo, g_bqlo);
    cudaGetSymbolAddress(&p_bphi, g_bphi);
    cudaGetSymbolAddress(&p_bplo, g_bplo);

    cudaFuncSetAttribute(gemm_mma_kernel, cudaFuncAttributeMaxDynamicSharedMemorySize, GDYN);

    rownorm_kernel<<<MROWS, 256>>>(x, (float*)p_x2a);
    colnorm_kernel<<<F_QKV / 256, 256>>>(w_qkv, F_QKV, (float*)p_k2a);
    colnorm_kernel<<<CC / 256, 256>>>(w_proj, CC, (float*)p_k2b);
    split_kernel<<<MROWS * CC / 256, 256>>>(x, (__nv_bfloat16*)p_ahi, (__nv_bfloat16*)p_alo);
    {
        dim3 g(F_QKV / 32, CC / 32);
        tsplit_kernel<<<g, 256>>>(w_qkv, F_QKV, (__nv_bfloat16*)p_bqhi, (__nv_bfloat16*)p_bqlo);
    }
    {
        dim3 g(CC / 32, CC / 32);
        tsplit_kernel<<<g, 256>>>(w_proj, CC, (__nv_bfloat16*)p_bphi, (__nv_bfloat16*)p_bplo);
    }

    {
        dim3 grid(F_QKV / 128, MROWS / 128);
        gemm_mma_kernel<<<grid, 256, GDYN>>>(
            (const __nv_bfloat16*)p_ahi, (const __nv_bfloat16*)p_alo,
            (const __nv_bfloat16*)p_bqhi, (const __nv_bfloat16*)p_bqlo,
            (const float*)p_x2a, (const float*)p_k2a, b_qkv, alpha_qkv,
            F_QKV, 0, nullptr);
    }

    // attention prep
    {
        int nrows = BATCH * NHEADS_EFF * TT;
        norm16_kernel<<<nrows / 256, 256>>>((const float*)p_q, (float*)p_qq);
        norm16_kernel<<<nrows / 256, 256>>>((const float*)p_k, (float*)p_kk);
        qksplit_kernel<<<(BATCH * NHEADS_EFF * TT * HD_EFF) / 4 / 256, 256>>>();
        dim3 gv(TT / 128, NHEADS_EFF, BATCH);
        vtsplit_kernel<<<gv, 256>>>();
    }

    // tensor-core attention
    {
        dim3 grid(TT / 128, NHEADS_EFF, BATCH);
        attn_mma_kernel<<<grid, 256>>>(alpha_attn);
    }

    rownorm_kernel<<<MROWS, 256>>>((const float*)p_att, (float*)p_x2b);
    split_kernel<<<MROWS * CC / 256, 256>>>((const float*)p_att,
                                            (__nv_bfloat16*)p_ahi, (__nv_bfloat16*)p_alo);
    {
        dim3 grid(CC / 128, MROWS / 128);
        gemm_mma_kernel<<<grid, 256, GDYN>>>(
            (const __nv_bfloat16*)p_ahi, (const __nv_bfloat16*)p_alo,
            (const __nv_bfloat16*)p_bphi, (const __nv_bfloat16*)p_bplo,
            (const float*)p_x2b, (const float*)p_k2b, b_proj, alpha_proj,
            CC, 1, out);
    }
}

// round 6
// speedup vs baseline: 2.8880x; 1.4101x over previous
#include <cuda_runtime.h>
#include <cuda_bf16.h>
#include <math.h>
#include <stdint.h>

#define EPS_C (1.0f/137.0f)

#define BATCH 2
#define TT 1024
#define CC 1024
#define F_QKV 3072
#define MROWS (BATCH*TT)
#define NHEADS_EFF 64
#define HD_EFF 16

typedef unsigned long long u64;

// ---------------- scratch ----------------
__device__ float g_q[BATCH*NHEADS_EFF*TT*HD_EFF];
__device__ float g_k[BATCH*NHEADS_EFF*TT*HD_EFF];
__device__ float g_v[BATCH*NHEADS_EFF*TT*HD_EFF];
__device__ float g_att[MROWS*CC];
__device__ float g_x2a[MROWS];
__device__ float g_x2b[MROWS];
__device__ float g_k2a[F_QKV];
__device__ float g_k2b[CC];
__device__ float g_kk[BATCH*NHEADS_EFF*TT];
__device__ float g_qq[BATCH*NHEADS_EFF*TT];

__device__ __nv_bfloat16 g_ahi[MROWS*CC];
__device__ __nv_bfloat16 g_alo[MROWS*CC];
__device__ __nv_bfloat16 g_bqhi[F_QKV*CC];
__device__ __nv_bfloat16 g_bqlo[F_QKV*CC];
__device__ __nv_bfloat16 g_bphi[CC*CC];
__device__ __nv_bfloat16 g_bplo[CC*CC];

__device__ __nv_bfloat16 g_qhi[BATCH*NHEADS_EFF*TT*HD_EFF];
__device__ __nv_bfloat16 g_qlo[BATCH*NHEADS_EFF*TT*HD_EFF];
__device__ __nv_bfloat16 g_khi[BATCH*NHEADS_EFF*TT*HD_EFF];
__device__ __nv_bfloat16 g_klo[BATCH*NHEADS_EFF*TT*HD_EFF];
__device__ __nv_bfloat16 g_vthi[BATCH*NHEADS_EFF*HD_EFF*TT];
__device__ __nv_bfloat16 g_vtlo[BATCH*NHEADS_EFF*HD_EFF*TT];

// ---------------- helpers ----------------
__device__ __forceinline__ unsigned smem_u32(const void* p) {
    return (unsigned)__cvta_generic_to_shared(p);
}
__device__ __forceinline__ void cp_async16(unsigned dst, const void* src) {
    asm volatile("cp.async.cg.shared.global [%0], [%1], 16;" :: "r"(dst), "l"(src));
}
__device__ __forceinline__ void cp_commit() { asm volatile("cp.async.commit_group;"); }
__device__ __forceinline__ void cp_wait0()  { asm volatile("cp.async.wait_group 0;"); }
__device__ __forceinline__ void cp_wait1()  { asm volatile("cp.async.wait_group 1;"); }

__device__ __forceinline__ void ldsm4(uint32_t* r, uint32_t addr) {
    asm volatile("ldmatrix.sync.aligned.m8n8.x4.shared.b16 {%0,%1,%2,%3},[%4];"
        : "=r"(r[0]), "=r"(r[1]), "=r"(r[2]), "=r"(r[3]) : "r"(addr));
}
__device__ __forceinline__ void mma16816(float* c, const uint32_t* a, const uint32_t* b) {
    asm volatile("mma.sync.aligned.m16n8k16.row.col.f32.bf16.bf16.f32 "
        "{%0,%1,%2,%3},{%4,%5,%6,%7},{%8,%9},{%0,%1,%2,%3};"
        : "+f"(c[0]), "+f"(c[1]), "+f"(c[2]), "+f"(c[3])
        : "r"(a[0]), "r"(a[1]), "r"(a[2]), "r"(a[3]), "r"(b[0]), "r"(b[1]));
}
__device__ __forceinline__ uint32_t pkbf(float lo, float hi) {
    uint32_t r; asm("cvt.rn.bf16x2.f32 %0,%1,%2;" : "=r"(r) : "f"(hi), "f"(lo)); return r;
}
__device__ __forceinline__ float2 ubf(uint32_t u) {
    __nv_bfloat162 h = *reinterpret_cast<__nv_bfloat162*>(&u);
    return __bfloat1622float2(h);
}

// ---------------- row norms (+ optional zero of colnorm accumulators) ----------------
__global__ void rownorm_kernel(const float* __restrict__ src, float* __restrict__ dst, int zero) {
    if (zero && blockIdx.x < 16) {
        int idx = blockIdx.x * 256 + threadIdx.x;
        if (idx < F_QKV) g_k2a[idx] = 0.f;
        else g_k2b[idx - F_QKV] = 0.f;
    }
    int row = blockIdx.x;
    const float* base = src + (size_t)row * CC;
    float s = 0.f;
    for (int c = threadIdx.x; c < CC; c += 256) {
        float v = base[c];
        s = fmaf(v, v, s);
    }
    #pragma unroll
    for (int off = 16; off; off >>= 1) s += __shfl_xor_sync(~0u, s, off);
    __shared__ float red[8];
    if ((threadIdx.x & 31) == 0) red[threadIdx.x >> 5] = s;
    __syncthreads();
    if (threadIdx.x == 0) {
        float t = 0.f;
        #pragma unroll
        for (int i = 0; i < 8; i++) t += red[i];
        dst[row] = t;
    }
}

// ---------------- bf16 split (A operand) ----------------
__global__ void split_kernel(const float* __restrict__ src,
                             __nv_bfloat16* __restrict__ hi, __nv_bfloat16* __restrict__ lo) {
    int i = blockIdx.x * 256 + threadIdx.x;
    float v = src[i];
    __nv_bfloat16 h = __float2bfloat16(v);
    float r = v - __bfloat162float(h);
    hi[i] = h;
    lo[i] = __float2bfloat16(r);
}

// ---------------- bf16 split + transpose + fused column norm ----------------
__global__ void tsplit_kernel(const float* __restrict__ w, int N,
                              __nv_bfloat16* __restrict__ hiT, __nv_bfloat16* __restrict__ loT,
                              float* __restrict__ cnorm) {
    __shared__ float tile[32][33];
    int n0 = blockIdx.x * 32, k0 = blockIdx.y * 32;
    int tx = threadIdx.x & 31, ty = threadIdx.x >> 5;
    #pragma unroll
    for (int r = 0; r < 32; r += 8)
        tile[ty + r][tx] = w[(size_t)(k0 + ty + r) * N + n0 + tx];
    __syncthreads();
    #pragma unroll
    for (int r = 0; r < 32; r += 8) {
        float v = tile[tx][ty + r];              // column n0+ty+r, k = k0+tx
        __nv_bfloat16 h = __float2bfloat16(v);
        float res = v - __bfloat162float(h);
        size_t idx = (size_t)(n0 + ty + r) * CC + k0 + tx;
        hiT[idx] = h;
        loT[idx] = __float2bfloat16(res);
        // warp-reduce v^2 over tx (all lanes share column) -> one atomic per warp
        float s = v * v;
        #pragma unroll
        for (int off = 16; off; off >>= 1) s += __shfl_xor_sync(~0u, s, off);
        if (tx == 0) atomicAdd(&cnorm[n0 + ty + r], s);
    }
}

// ---------------- fused q/k norms + bf16 splits ----------------
__global__ void qkprep_kernel() {
    size_t r = (size_t)blockIdx.x * 256 + threadIdx.x;   // row id
    const float4* qp = (const float4*)(g_q + r * 16);
    const float4* kp = (const float4*)(g_k + r * 16);
    float qv[16], kv[16];
    #pragma unroll
    for (int e = 0; e < 4; e++) {
        float4 a = qp[e];
        qv[4*e] = a.x; qv[4*e+1] = a.y; qv[4*e+2] = a.z; qv[4*e+3] = a.w;
        float4 b = kp[e];
        kv[4*e] = b.x; kv[4*e+1] = b.y; kv[4*e+2] = b.z; kv[4*e+3] = b.w;
    }
    float qn = 0.f, kn = 0.f;
    #pragma unroll
    for (int e = 0; e < 16; e++) { qn = fmaf(qv[e], qv[e], qn); kn = fmaf(kv[e], kv[e], kn); }
    g_qq[r] = qn;
    g_kk[r] = kn;
    uint4 qh, ql, kh, kl;
    uint32_t *qhp = (uint32_t*)&qh, *qlp = (uint32_t*)&ql;
    uint32_t *khp = (uint32_t*)&kh, *klp = (uint32_t*)&kl;
    #pragma unroll
    for (int e = 0; e < 4; e++) {
        float x0 = qv[2*e], x1 = qv[2*e+1];
        __nv_bfloat16 h0 = __float2bfloat16(x0), h1 = __float2bfloat16(x1);
        qhp[e] = pkbf(x0, x1);
        qlp[e] = pkbf(x0 - __bfloat162float(h0), x1 - __bfloat162float(h1));
        float y0 = kv[2*e], y1 = kv[2*e+1];
        __nv_bfloat16 g0 = __float2bfloat16(y0), g1 = __float2bfloat16(y1);
        khp[e] = pkbf(y0, y1);
        klp[e] = pkbf(y0 - __bfloat162float(g0), y1 - __bfloat162float(g1));
    }
    *(uint4*)&g_qhi[r*16] = qh;
    *(uint4*)&g_klo[r*16+8] = kl;   // interleave writes to spread sectors
    uint4 qh2, ql2, kh2, kl2;
    uint32_t *qhp2 = (uint32_t*)&qh2, *qlp2 = (uint32_t*)&ql2;
    uint32_t *khp2 = (uint32_t*)&kh2, *klp2 = (uint32_t*)&kl2;
    #pragma unroll
    for (int e = 0; e < 4; e++) {
        float x0 = qv[8+2*e], x1 = qv[8+2*e+1];
        __nv_bfloat16 h0 = __float2bfloat16(x0), h1 = __float2bfloat16(x1);
        qhp2[e] = pkbf(x0, x1);
        qlp2[e] = pkbf(x0 - __bfloat162float(h0), x1 - __bfloat162float(h1));
        float y0 = kv[8+2*e], y1 = kv[8+2*e+1];
        __nv_bfloat16 g0 = __float2bfloat16(y0), g1 = __float2bfloat16(y1);
        khp2[e] = pkbf(y0, y1);
        klp2[e] = pkbf(y0 - __bfloat162float(g0), y1 - __bfloat162float(g1));
    }
    *(uint4*)&g_qhi[r*16+8] = qh2;
    *(uint4*)&g_qlo[r*16]   = ql;
    *(uint4*)&g_qlo[r*16+8] = ql2;
    *(uint4*)&g_khi[r*16]   = kh;
    *(uint4*)&g_khi[r*16+8] = kh2;
    *(uint4*)&g_klo[r*16]   = kl2;
    // fix interleaved writes: g_klo[r*16+8] got kl (first half) and g_klo[r*16] got kl2 — swap back
}

// NOTE: the interleave above was wrong-ordered; use a corrected simple version instead.
__global__ void qkprep2_kernel() {
    size_t r = (size_t)blockIdx.x * 256 + threadIdx.x;
    const float4* qp = (const float4*)(g_q + r * 16);
    const float4* kp = (const float4*)(g_k + r * 16);
    float qv[16], kv[16];
    #pragma unroll
    for (int e = 0; e < 4; e++) {
        float4 a = qp[e];
        qv[4*e] = a.x; qv[4*e+1] = a.y; qv[4*e+2] = a.z; qv[4*e+3] = a.w;
        float4 b = kp[e];
        kv[4*e] = b.x; kv[4*e+1] = b.y; kv[4*e+2] = b.z; kv[4*e+3] = b.w;
    }
    float qn = 0.f, kn = 0.f;
    #pragma unroll
    for (int e = 0; e < 16; e++) { qn = fmaf(qv[e], qv[e], qn); kn = fmaf(kv[e], kv[e], kn); }
    g_qq[r] = qn;
    g_kk[r] = kn;
    uint32_t qh[8], ql[8], kh[8], kl[8];
    #pragma unroll
    for (int e = 0; e < 8; e++) {
        float x0 = qv[2*e], x1 = qv[2*e+1];
        __nv_bfloat16 h0 = __float2bfloat16(x0), h1 = __float2bfloat16(x1);
        qh[e] = pkbf(x0, x1);
        ql[e] = pkbf(x0 - __bfloat162float(h0), x1 - __bfloat162float(h1));
        float y0 = kv[2*e], y1 = kv[2*e+1];
        __nv_bfloat16 g0 = __float2bfloat16(y0), g1 = __float2bfloat16(y1);
        kh[e] = pkbf(y0, y1);
        kl[e] = pkbf(y0 - __bfloat162float(g0), y1 - __bfloat162float(g1));
    }
    *(uint4*)&g_qhi[r*16]   = *(uint4*)&qh[0];
    *(uint4*)&g_qhi[r*16+8] = *(uint4*)&qh[4];
    *(uint4*)&g_qlo[r*16]   = *(uint4*)&ql[0];
    *(uint4*)&g_qlo[r*16+8] = *(uint4*)&ql[4];
    *(uint4*)&g_khi[r*16]   = *(uint4*)&kh[0];
    *(uint4*)&g_khi[r*16+8] = *(uint4*)&kh[4];
    *(uint4*)&g_klo[r*16]   = *(uint4*)&kl[0];
    *(uint4*)&g_klo[r*16+8] = *(uint4*)&kl[4];
}

// ---------------- v transpose + split ----------------
__global__ void vtsplit_kernel() {
    __shared__ float ts[16][132];
    const int tid = threadIdx.x;
    const int t0 = blockIdx.x * 128;
    const size_t hb = (size_t)(blockIdx.z * NHEADS_EFF + blockIdx.y) * TT * HD_EFF;
    const float* src = g_v + hb + (size_t)t0 * 16;
    {
        int t = tid >> 1, h0 = (tid & 1) * 8;
        float4 v0 = *(const float4*)&src[t * 16 + h0];
        float4 v1 = *(const float4*)&src[t * 16 + h0 + 4];
        ts[h0 + 0][t] = v0.x; ts[h0 + 1][t] = v0.y; ts[h0 + 2][t] = v0.z; ts[h0 + 3][t] = v0.w;
        ts[h0 + 4][t] = v1.x; ts[h0 + 5][t] = v1.y; ts[h0 + 6][t] = v1.z; ts[h0 + 7][t] = v1.w;
    }
    __syncthreads();
    int h = tid >> 4, c = (tid & 15) * 8;
    uint4 hiv, lov;
    uint32_t* hp = (uint32_t*)&hiv;
    uint32_t* lp = (uint32_t*)&lov;
    #pragma unroll
    for (int e = 0; e < 4; e++) {
        float x = ts[h][c + 2 * e], y = ts[h][c + 2 * e + 1];
        __nv_bfloat16 hx = __float2bfloat16(x), hy = __float2bfloat16(y);
        hp[e] = pkbf(x, y);
        lp[e] = pkbf(x - __bfloat162float(hx), y - __bfloat162float(hy));
    }
    size_t dst = hb + (size_t)h * TT + t0 + c;
    *(uint4*)&g_vthi[dst] = hiv;
    *(uint4*)&g_vtlo[dst] = lov;
}

// ---------------- mma.sync GEMM + YAT epilogue ----------------
#define GBK 32
#define ROWPAD 40
#define TILE_B (128*ROWPAD*2)
#define BUF_B  (4*TILE_B)
#define GDYN   (2*BUF_B)

__global__ __launch_bounds__(256, 1)
void gemm_mma_kernel(const __nv_bfloat16* __restrict__ Ahi, const __nv_bfloat16* __restrict__ Alo,
                     const __nv_bfloat16* __restrict__ BhiT, const __nv_bfloat16* __restrict__ BloT,
                     const float* __restrict__ x2, const float* __restrict__ k2,
                     const float* __restrict__ bias, const float* __restrict__ alpha,
                     int N, int mode, float* __restrict__ outP) {
    extern __shared__ char smem[];
    const uint32_t sb = smem_u32(smem);
    const int tid = threadIdx.x;
    const int wid = tid >> 5, lane = tid & 31;
    const int wr = wid >> 2, wc = wid & 3;
    const int m0 = blockIdx.y * 128, n0 = blockIdx.x * 128;

    const __nv_bfloat16* srcs[4] = {
        Ahi + (size_t)m0 * CC, Alo + (size_t)m0 * CC,
        BhiT + (size_t)n0 * CC, BloT + (size_t)n0 * CC };

    float acc[4][4][4];
    #pragma unroll
    for (int i = 0; i < 4; i++)
        #pragma unroll
        for (int j = 0; j < 4; j++)
            #pragma unroll
            for (int e = 0; e < 4; e++) acc[i][j][e] = 0.f;

    const int grp = lane >> 3;
    const uint32_t aRow = (uint32_t)((wr*64 + (grp&1)*8 + (lane&7)) * (ROWPAD*2) + (grp>>1)*16);
    const uint32_t bRow = (uint32_t)((wc*32 + (grp>>1)*8 + (lane&7)) * (ROWPAD*2) + (grp&1)*16);

    const int NT = CC / GBK;

    {
        const uint32_t bufb = sb;
        #pragma unroll
        for (int t4 = 0; t4 < 4; t4++) {
            #pragma unroll
            for (int i = 0; i < 2; i++) {
                int idx = tid + 256 * i;
                int r = idx >> 2, c = idx & 3;
                uint32_t dst = bufb + t4*TILE_B + (uint32_t)(r*(ROWPAD*2) + c*16);
                cp_async16(dst, srcs[t4] + (size_t)r * CC + c*8);
            }
        }
        cp_commit();
    }

    for (int kt = 0; kt < NT; kt++) {
        const uint32_t cur = sb + (kt & 1) * BUF_B;
        if (kt < NT - 1) {
            const uint32_t nxtb = sb + ((kt + 1) & 1) * BUF_B;
            const int k0 = (kt + 1) * GBK;
            #pragma unroll
            for (int t4 = 0; t4 < 4; t4++) {
                #pragma unroll
                for (int i = 0; i < 2; i++) {
                    int idx = tid + 256 * i;
                    int r = idx >> 2, c = idx & 3;
                    uint32_t dst = nxtb + t4*TILE_B + (uint32_t)(r*(ROWPAD*2) + c*16);
                    cp_async16(dst, srcs[t4] + (size_t)r * CC + k0 + c*8);
                }
            }
            cp_commit();
            cp_wait1();
        } else {
            cp_wait0();
        }
        __syncthreads();

        #pragma unroll
        for (int k16 = 0; k16 < 2; k16++) {
            const uint32_t ko = (uint32_t)(k16 * 32);
            uint32_t ah[4][4], al[4][4], bh[2][4], bl[2][4];
            #pragma unroll
            for (int mt = 0; mt < 4; mt++) {
                ldsm4(ah[mt], cur + 0*TILE_B + aRow + (uint32_t)(mt*16*(ROWPAD*2)) + ko);
                ldsm4(al[mt], cur + 1*TILE_B + aRow + (uint32_t)(mt*16*(ROWPAD*2)) + ko);
            }
            #pragma unroll
            for (int nt = 0; nt < 2; nt++) {
                ldsm4(bh[nt], cur + 2*TILE_B + bRow + (uint32_t)(nt*16*(ROWPAD*2)) + ko);
                ldsm4(bl[nt], cur + 3*TILE_B + bRow + (uint32_t)(nt*16*(ROWPAD*2)) + ko);
            }
            #pragma unroll
            for (int mt = 0; mt < 4; mt++) {
                #pragma unroll
                for (int nt = 0; nt < 4; nt++) {
                    const uint32_t* bhp = &bh[nt >> 1][(nt & 1) * 2];
                    const uint32_t* blp = &bl[nt >> 1][(nt & 1) * 2];
                    mma16816(acc[mt][nt], ah[mt], bhp);
                    mma16816(acc[mt][nt], ah[mt], blp);
                    mma16816(acc[mt][nt], al[mt], bhp);
                }
            }
        }
        __syncthreads();
    }

    const float scale = powf(sqrtf((float)N) / log1pf((float)N), alpha[0]);
    const int mbase = m0 + wr*64 + (lane >> 2);
    const int nbase = n0 + wc*32 + (lane & 3)*2;

    #pragma unroll
    for (int mt = 0; mt < 4; mt++) {
        #pragma unroll
        for (int half = 0; half < 2; half++) {
            const int gm = mbase + mt*16 + half*8;
            const float x2v = x2[gm];
            const int bb = gm >> 10, t = gm & 1023;
            #pragma unroll
            for (int nt = 0; nt < 4; nt++) {
                float y0 = acc[mt][nt][half*2 + 0];
                float y1 = acc[mt][nt][half*2 + 1];
                const int gn = nbase + nt*8;
                float k20 = k2[gn], k21 = k2[gn+1];
                float b0 = bias[gn], b1 = bias[gn+1];
                float v0 = (y0*y0) / (x2v + k20 - 2.f*y0 + EPS_C) * scale + b0;
                float v1 = (y1*y1) / (x2v + k21 - 2.f*y1 + EPS_C) * scale + b1;
                if (mode == 0) {
                    #pragma unroll
                    for (int e = 0; e < 2; e++) {
                        int g = gn + e;
                        float val = e ? v1 : v0;
                        int s = g >> 10;
                        int hh = (g & 1023) >> 6;
                        int dd = g & 63;
                        size_t idx = (((size_t)(bb * NHEADS_EFF + dd) * TT) + t) * HD_EFF + hh;
                        if (s == 0) g_q[idx] = val;
                        else if (s == 1) g_k[idx] = val;
                        else g_v[idx] = val;
                    }
                } else {
                    float2 o; o.x = v0; o.y = v1;
                    *(float2*)(outP + (size_t)gm * N + gn) = o;
                }
            }
        }
    }
}

// ---------------- tensor-core attention ----------------
__global__ __launch_bounds__(256, 2)
void attn_mma_kernel(const float* __restrict__ alpha_attn) {
    __shared__ __nv_bfloat16 Kh[128*24];
    __shared__ __nv_bfloat16 Kl[128*24];
    __shared__ __nv_bfloat16 VTh[16*136];
    __shared__ __nv_bfloat16 VTl[16*136];
    __shared__ float k2s[128];

    const int tid = threadIdx.x, lane = tid & 31, wr = tid >> 5;
    const int g = lane >> 2, tc = lane & 3;
    const int itile = blockIdx.x, dh = blockIdx.y, b = blockIdx.z;
    const int i0 = itile * 128;
    const size_t hb = (size_t)(b * NHEADS_EFF + dh) * TT * HD_EFF;
    const size_t nb = (size_t)(b * NHEADS_EFF + dh) * TT;

    const float inv_scale = powf(64.0f / log1pf(64.0f), alpha_attn[0]);

    const int r0 = i0 + wr * 16 + g;

    uint32_t aq_h[4], aq_l[4];
    {
        const __nv_bfloat16* qh = g_qhi + hb;
        const __nv_bfloat16* ql = g_qlo + hb;
        aq_h[0] = *(const uint32_t*)&qh[(size_t)r0 * 16 + 2*tc];
        aq_h[1] = *(const uint32_t*)&qh[(size_t)(r0+8) * 16 + 2*tc];
        aq_h[2] = *(const uint32_t*)&qh[(size_t)r0 * 16 + 8 + 2*tc];
        aq_h[3] = *(const uint32_t*)&qh[(size_t)(r0+8) * 16 + 8 + 2*tc];
        aq_l[0] = *(const uint32_t*)&ql[(size_t)r0 * 16 + 2*tc];
        aq_l[1] = *(const uint32_t*)&ql[(size_t)(r0+8) * 16 + 2*tc];
        aq_l[2] = *(const uint32_t*)&ql[(size_t)r0 * 16 + 8 + 2*tc];
        aq_l[3] = *(const uint32_t*)&ql[(size_t)(r0+8) * 16 + 8 + 2*tc];
    }
    const float q20 = g_qq[nb + r0] + EPS_C;
    const float q21 = g_qq[nb + r0 + 8] + EPS_C;

    float O0[8];
    #pragma unroll
    for (int e = 0; e < 8; e++) O0[e] = 0.f;
    float l0 = 0.f, l1 = 0.f;

    for (int jt = 0; jt <= itile; jt++) {
        const int j0 = jt * 128;
        __syncthreads();
        {
            int row = tid >> 1, hcol = (tid & 1) * 8;
            *(uint4*)&Kh[row*24 + hcol] = *(const uint4*)&g_khi[hb + (size_t)(j0 + row)*16 + hcol];
            *(uint4*)&Kl[row*24 + hcol] = *(const uint4*)&g_klo[hb + (size_t)(j0 + row)*16 + hcol];
            int vrow = tid >> 4, vcol = (tid & 15) * 8;
            *(uint4*)&VTh[vrow*136 + vcol] = *(const uint4*)&g_vthi[hb + (size_t)vrow*TT + j0 + vcol];
            *(uint4*)&VTl[vrow*136 + vcol] = *(const uint4*)&g_vtlo[hb + (size_t)vrow*TT + j0 + vcol];
            if (tid < 128) k2s[tid] = g_kk[nb + j0 + tid];
        }
        __syncthreads();

        float S[16][4];
        #pragma unroll
        for (int nt = 0; nt < 16; nt++) {
            uint32_t bh[2], bl[2];
            int kr = (nt*8 + g) * 24 + 2*tc;
            bh[0] = *(const uint32_t*)&Kh[kr];
            bh[1] = *(const uint32_t*)&Kh[kr + 8];
            bl[0] = *(const uint32_t*)&Kl[kr];
            bl[1] = *(const uint32_t*)&Kl[kr + 8];
            S[nt][0] = S[nt][1] = S[nt][2] = S[nt][3] = 0.f;
            mma16816(S[nt], aq_h, bh);
            mma16816(S[nt], aq_h, bl);
            mma16816(S[nt], aq_l, bh);
        }

        const bool maskt = (jt == itile);
        #pragma unroll
        for (int nt = 0; nt < 16; nt++) {
            #pragma unroll
            for (int c = 0; c < 4; c++) {
                float s = S[nt][c];
                float k2v = k2s[nt*8 + 2*tc + (c & 1)];
                float q2v = (c < 2) ? q20 : q21;
                float den = fmaf(-2.f, s, q2v + k2v);
                float p = __expf(__fdividef(s * s * inv_scale, den));
                if (maskt) {
                    int j = j0 + nt*8 + 2*tc + (c & 1);
                    int iq = (c < 2) ? r0 : r0 + 8;
                    if (j > iq) p = 0.f;
                }
                if (c < 2) l0 += p; else l1 += p;
                S[nt][c] = p;
            }
        }

        #pragma unroll
        for (int kb = 0; kb < 8; kb++) {
            float* Sa = S[2*kb];
            float* Sb = S[2*kb + 1];
            uint32_t ph[4], pl[4];
            ph[0] = pkbf(Sa[0], Sa[1]);
            ph[1] = pkbf(Sa[2], Sa[3]);
            ph[2] = pkbf(Sb[0], Sb[1]);
            ph[3] = pkbf(Sb[2], Sb[3]);
            float2 f;
            f = ubf(ph[0]); pl[0] = pkbf(Sa[0] - f.x, Sa[1] - f.y);
            f = ubf(ph[1]); pl[1] = pkbf(Sa[2] - f.x, Sa[3] - f.y);
            f = ubf(ph[2]); pl[2] = pkbf(Sb[0] - f.x, Sb[1] - f.y);
            f = ubf(ph[3]); pl[3] = pkbf(Sb[2] - f.x, Sb[3] - f.y);
            #pragma unroll
            for (int dt = 0; dt < 2; dt++) {
                uint32_t bvh[2], bvl[2];
                int vr = (dt*8 + g) * 136 + kb*16 + 2*tc;
                bvh[0] = *(const uint32_t*)&VTh[vr];
                bvh[1] = *(const uint32_t*)&VTh[vr + 8];
                bvl[0] = *(const uint32_t*)&VTl[vr];
                bvl[1] = *(const uint32_t*)&VTl[vr + 8];
                float* Od = &O0[dt*4];
                mma16816(Od, ph, bvh);
                mma16816(Od, ph, bvl);
                mma16816(Od, pl, bvh);
            }
        }
    }

    l0 += __shfl_xor_sync(~0u, l0, 1); l0 += __shfl_xor_sync(~0u, l0, 2);
    l1 += __shfl_xor_sync(~0u, l1, 1); l1 += __shfl_xor_sync(~0u, l1, 2);
    const float inv0 = 1.f / l0, inv1 = 1.f / l1;

    float* ob0 = g_att + (size_t)(b*TT + r0) * CC + dh*16;
    float* ob1 = g_att + (size_t)(b*TT + r0 + 8) * CC + dh*16;
    #pragma unroll
    for (int dt = 0; dt < 2; dt++) {
        int col = dt*8 + 2*tc;
        float2 o0; o0.x = O0[dt*4+0]*inv0; o0.y = O0[dt*4+1]*inv0;
        float2 o1; o1.x = O0[dt*4+2]*inv1; o1.y = O0[dt*4+3]*inv1;
        *(float2*)&ob0[col] = o0;
        *(float2*)&ob1[col] = o1;
    }
}

// ---------------- launch ----------------
extern "C" void kernel_launch(void* const* d_in, const int* in_sizes, int n_in,
                              void* d_out, int out_size) {
    const float* x          = (const float*)d_in[0];
    const float* w_qkv      = (const float*)d_in[2];
    const float* b_qkv      = (const float*)d_in[3];
    const float* alpha_qkv  = (const float*)d_in[4];
    const float* w_proj     = (const float*)d_in[5];
    const float* b_proj     = (const float*)d_in[6];
    const float* alpha_proj = (const float*)d_in[7];
    const float* alpha_attn = (const float*)d_in[8];
    float* out = (float*)d_out;

    void *p_att, *p_x2a, *p_x2b, *p_k2a, *p_k2b;
    void *p_ahi, *p_alo, *p_bqhi, *p_bqlo, *p_bphi, *p_bplo;
    cudaGetSymbolAddress(&p_att,  g_att);
    cudaGetSymbolAddress(&p_x2a,  g_x2a);
    cudaGetSymbolAddress(&p_x2b,  g_x2b);
    cudaGetSymbolAddress(&p_k2a,  g_k2a);
    cudaGetSymbolAddress(&p_k2b,  g_k2b);
    cudaGetSymbolAddress(&p_ahi,  g_ahi);
    cudaGetSymbolAddress(&p_alo,  g_alo);
    cudaGetSymbolAddress(&p_bqhi, g_bqhi);
    cudaGetSymbolAddress(&p_bqlo, g_bqlo);
    cudaGetSymbolAddress(&p_bphi, g_bphi);
    cudaGetSymbolAddress(&p_bplo, g_bplo);

    cudaFuncSetAttribute(gemm_mma_kernel, cudaFuncAttributeMaxDynamicSharedMemorySize, GDYN);

    // (1) row norms of x + zero the fused column-norm accumulators
    rownorm_kernel<<<MROWS, 256>>>(x, (float*)p_x2a, 1);
    // (2) x split
    split_kernel<<<MROWS * CC / 256, 256>>>(x, (__nv_bfloat16*)p_ahi, (__nv_bfloat16*)p_alo);
    // (3) w_qkv transpose+split+colnorm
    {
        dim3 g(F_QKV / 32, CC / 32);
        tsplit_kernel<<<g, 256>>>(w_qkv, F_QKV, (__nv_bfloat16*)p_bqhi, (__nv_bfloat16*)p_bqlo,
                                  (float*)p_k2a);
    }
    // (4) qkv GEMM  <-- profiled launch
    {
        dim3 grid(F_QKV / 128, MROWS / 128);
        gemm_mma_kernel<<<grid, 256, GDYN>>>(
            (const __nv_bfloat16*)p_ahi, (const __nv_bfloat16*)p_alo,
            (const __nv_bfloat16*)p_bqhi, (const __nv_bfloat16*)p_bqlo,
            (const float*)p_x2a, (const float*)p_k2a, b_qkv, alpha_qkv,
            F_QKV, 0, nullptr);
    }
    // (5) w_proj transpose+split+colnorm
    {
        dim3 g(CC / 32, CC / 32);
        tsplit_kernel<<<g, 256>>>(w_proj, CC, (__nv_bfloat16*)p_bphi, (__nv_bfloat16*)p_bplo,
                                  (float*)p_k2b);
    }
    // (6) fused q/k norms + splits
    qkprep2_kernel<<<(BATCH * NHEADS_EFF * TT) / 256, 256>>>();
    // (7) v transpose + split
    {
        dim3 gv(TT / 128, NHEADS_EFF, BATCH);
        vtsplit_kernel<<<gv, 256>>>();
    }
    // (8) attention
    {
        dim3 grid(TT / 128, NHEADS_EFF, BATCH);
        attn_mma_kernel<<<grid, 256>>>(alpha_attn);
    }
    // (9) att row norms
    rownorm_kernel<<<MROWS, 256>>>((const float*)p_att, (float*)p_x2b, 0);
    // (10) att split
    split_kernel<<<MROWS * CC / 256, 256>>>((const float*)p_att,
                                            (__nv_bfloat16*)p_ahi, (__nv_bfloat16*)p_alo);
    // (11) proj GEMM
    {
        dim3 grid(CC / 128, MROWS / 128);
        gemm_mma_kernel<<<grid, 256, GDYN>>>(
            (const __nv_bfloat16*)p_ahi, (const __nv_bfloat16*)p_alo,
            (const __nv_bfloat16*)p_bphi, (const __nv_bfloat16*)p_bplo,
            (const float*)p_x2b, (const float*)p_k2b, b_proj, alpha_proj,
            CC, 1, out);
    }
}

// round 7
// speedup vs baseline: 3.2616x; 1.1294x over previous
#include <cuda_runtime.h>
#include <cuda_bf16.h>
#include <math.h>
#include <stdint.h>

#define EPS_C (1.0f/137.0f)

#define BATCH 2
#define TT 1024
#define CC 1024
#define F_QKV 3072
#define MROWS (BATCH*TT)
#define NHEADS_EFF 64
#define HD_EFF 16

typedef unsigned long long u64;

// ---------------- scratch ----------------
__device__ float g_q[BATCH*NHEADS_EFF*TT*HD_EFF];
__device__ float g_k[BATCH*NHEADS_EFF*TT*HD_EFF];
__device__ float g_v[BATCH*NHEADS_EFF*TT*HD_EFF];
__device__ float g_att[MROWS*CC];
__device__ float g_x2a[MROWS];
__device__ float g_x2b[MROWS];
__device__ float g_k2a[F_QKV];
__device__ float g_k2b[CC];
__device__ float g_kk[BATCH*NHEADS_EFF*TT];
__device__ float g_qq[BATCH*NHEADS_EFF*TT];

__device__ __nv_bfloat16 g_ahi[MROWS*CC];
__device__ __nv_bfloat16 g_alo[MROWS*CC];
__device__ __nv_bfloat16 g_bqhi[F_QKV*CC];
__device__ __nv_bfloat16 g_bqlo[F_QKV*CC];
__device__ __nv_bfloat16 g_bphi[CC*CC];
__device__ __nv_bfloat16 g_bplo[CC*CC];

__device__ __nv_bfloat16 g_qhi[BATCH*NHEADS_EFF*TT*HD_EFF];
__device__ __nv_bfloat16 g_qlo[BATCH*NHEADS_EFF*TT*HD_EFF];
__device__ __nv_bfloat16 g_khi[BATCH*NHEADS_EFF*TT*HD_EFF];
__device__ __nv_bfloat16 g_klo[BATCH*NHEADS_EFF*TT*HD_EFF];
__device__ __nv_bfloat16 g_vthi[BATCH*NHEADS_EFF*HD_EFF*TT];
__device__ __nv_bfloat16 g_vtlo[BATCH*NHEADS_EFF*HD_EFF*TT];

// ---------------- helpers ----------------
__device__ __forceinline__ unsigned smem_u32(const void* p) {
    return (unsigned)__cvta_generic_to_shared(p);
}
__device__ __forceinline__ void cp_async16(unsigned dst, const void* src) {
    asm volatile("cp.async.cg.shared.global [%0], [%1], 16;" :: "r"(dst), "l"(src));
}
__device__ __forceinline__ void cp_commit() { asm volatile("cp.async.commit_group;"); }
__device__ __forceinline__ void cp_wait0()  { asm volatile("cp.async.wait_group 0;"); }
__device__ __forceinline__ void cp_wait1()  { asm volatile("cp.async.wait_group 1;"); }

__device__ __forceinline__ void ldsm4(uint32_t* r, uint32_t addr) {
    asm volatile("ldmatrix.sync.aligned.m8n8.x4.shared.b16 {%0,%1,%2,%3},[%4];"
        : "=r"(r[0]), "=r"(r[1]), "=r"(r[2]), "=r"(r[3]) : "r"(addr));
}
__device__ __forceinline__ void mma16816(float* c, const uint32_t* a, const uint32_t* b) {
    asm volatile("mma.sync.aligned.m16n8k16.row.col.f32.bf16.bf16.f32 "
        "{%0,%1,%2,%3},{%4,%5,%6,%7},{%8,%9},{%0,%1,%2,%3};"
        : "+f"(c[0]), "+f"(c[1]), "+f"(c[2]), "+f"(c[3])
        : "r"(a[0]), "r"(a[1]), "r"(a[2]), "r"(a[3]), "r"(b[0]), "r"(b[1]));
}
__device__ __forceinline__ uint32_t pkbf(float lo, float hi) {
    uint32_t r; asm("cvt.rn.bf16x2.f32 %0,%1,%2;" : "=r"(r) : "f"(hi), "f"(lo)); return r;
}
__device__ __forceinline__ float2 ubf(uint32_t u) {
    __nv_bfloat162 h = *reinterpret_cast<__nv_bfloat162*>(&u);
    return __bfloat1622float2(h);
}

// ---------------- fused row norms + bf16 split ----------------
__global__ void rowsplit_kernel(const float* __restrict__ src, float* __restrict__ dnorm,
                                __nv_bfloat16* __restrict__ hi, __nv_bfloat16* __restrict__ lo,
                                int zero) {
    const int row = blockIdx.x, tid = threadIdx.x;
    if (zero && row < 16) {
        int idx = row * 256 + tid;
        if (idx < F_QKV) g_k2a[idx] = 0.f;
        else g_k2b[idx - F_QKV] = 0.f;
    }
    float4 v = ((const float4*)(src + (size_t)row * CC))[tid];
    float s = v.x*v.x + v.y*v.y + v.z*v.z + v.w*v.w;
    __nv_bfloat16 h0 = __float2bfloat16(v.x), h1 = __float2bfloat16(v.y);
    __nv_bfloat16 h2 = __float2bfloat16(v.z), h3 = __float2bfloat16(v.w);
    uint2 hv, lv;
    hv.x = pkbf(v.x, v.y); hv.y = pkbf(v.z, v.w);
    lv.x = pkbf(v.x - __bfloat162float(h0), v.y - __bfloat162float(h1));
    lv.y = pkbf(v.z - __bfloat162float(h2), v.w - __bfloat162float(h3));
    *(uint2*)&hi[(size_t)row * CC + tid*4] = hv;
    *(uint2*)&lo[(size_t)row * CC + tid*4] = lv;
    #pragma unroll
    for (int off = 16; off; off >>= 1) s += __shfl_xor_sync(~0u, s, off);
    __shared__ float red[8];
    if ((tid & 31) == 0) red[tid >> 5] = s;
    __syncthreads();
    if (tid == 0) {
        float t = 0.f;
        #pragma unroll
        for (int i = 0; i < 8; i++) t += red[i];
        dnorm[row] = t;
    }
}

// ---------------- bf16 split + transpose + fused column norm ----------------
__global__ void tsplit_kernel(const float* __restrict__ w, int N,
                              __nv_bfloat16* __restrict__ hiT, __nv_bfloat16* __restrict__ loT,
                              float* __restrict__ cnorm) {
    __shared__ float tile[32][33];
    int n0 = blockIdx.x * 32, k0 = blockIdx.y * 32;
    int tx = threadIdx.x & 31, ty = threadIdx.x >> 5;
    #pragma unroll
    for (int r = 0; r < 32; r += 8)
        tile[ty + r][tx] = w[(size_t)(k0 + ty + r) * N + n0 + tx];
    __syncthreads();
    #pragma unroll
    for (int r = 0; r < 32; r += 8) {
        float v = tile[tx][ty + r];
        __nv_bfloat16 h = __float2bfloat16(v);
        float res = v - __bfloat162float(h);
        size_t idx = (size_t)(n0 + ty + r) * CC + k0 + tx;
        hiT[idx] = h;
        loT[idx] = __float2bfloat16(res);
        float s = v * v;
        #pragma unroll
        for (int off = 16; off; off >>= 1) s += __shfl_xor_sync(~0u, s, off);
        if (tx == 0) atomicAdd(&cnorm[n0 + ty + r], s);
    }
}

// ---------------- fused q/k norms + bf16 splits ----------------
__global__ void qkprep2_kernel() {
    size_t r = (size_t)blockIdx.x * 256 + threadIdx.x;
    const float4* qp = (const float4*)(g_q + r * 16);
    const float4* kp = (const float4*)(g_k + r * 16);
    float qv[16], kv[16];
    #pragma unroll
    for (int e = 0; e < 4; e++) {
        float4 a = qp[e];
        qv[4*e] = a.x; qv[4*e+1] = a.y; qv[4*e+2] = a.z; qv[4*e+3] = a.w;
        float4 b = kp[e];
        kv[4*e] = b.x; kv[4*e+1] = b.y; kv[4*e+2] = b.z; kv[4*e+3] = b.w;
    }
    float qn = 0.f, kn = 0.f;
    #pragma unroll
    for (int e = 0; e < 16; e++) { qn = fmaf(qv[e], qv[e], qn); kn = fmaf(kv[e], kv[e], kn); }
    g_qq[r] = qn;
    g_kk[r] = kn;
    uint32_t qh[8], ql[8], kh[8], kl[8];
    #pragma unroll
    for (int e = 0; e < 8; e++) {
        float x0 = qv[2*e], x1 = qv[2*e+1];
        __nv_bfloat16 h0 = __float2bfloat16(x0), h1 = __float2bfloat16(x1);
        qh[e] = pkbf(x0, x1);
        ql[e] = pkbf(x0 - __bfloat162float(h0), x1 - __bfloat162float(h1));
        float y0 = kv[2*e], y1 = kv[2*e+1];
        __nv_bfloat16 g0 = __float2bfloat16(y0), g1 = __float2bfloat16(y1);
        kh[e] = pkbf(y0, y1);
        kl[e] = pkbf(y0 - __bfloat162float(g0), y1 - __bfloat162float(g1));
    }
    *(uint4*)&g_qhi[r*16]   = *(uint4*)&qh[0];
    *(uint4*)&g_qhi[r*16+8] = *(uint4*)&qh[4];
    *(uint4*)&g_qlo[r*16]   = *(uint4*)&ql[0];
    *(uint4*)&g_qlo[r*16+8] = *(uint4*)&ql[4];
    *(uint4*)&g_khi[r*16]   = *(uint4*)&kh[0];
    *(uint4*)&g_khi[r*16+8] = *(uint4*)&kh[4];
    *(uint4*)&g_klo[r*16]   = *(uint4*)&kl[0];
    *(uint4*)&g_klo[r*16+8] = *(uint4*)&kl[4];
}

// ---------------- v transpose + split ----------------
__global__ void vtsplit_kernel() {
    __shared__ float ts[16][132];
    const int tid = threadIdx.x;
    const int t0 = blockIdx.x * 128;
    const size_t hb = (size_t)(blockIdx.z * NHEADS_EFF + blockIdx.y) * TT * HD_EFF;
    const float* src = g_v + hb + (size_t)t0 * 16;
    {
        int t = tid >> 1, h0 = (tid & 1) * 8;
        float4 v0 = *(const float4*)&src[t * 16 + h0];
        float4 v1 = *(const float4*)&src[t * 16 + h0 + 4];
        ts[h0 + 0][t] = v0.x; ts[h0 + 1][t] = v0.y; ts[h0 + 2][t] = v0.z; ts[h0 + 3][t] = v0.w;
        ts[h0 + 4][t] = v1.x; ts[h0 + 5][t] = v1.y; ts[h0 + 6][t] = v1.z; ts[h0 + 7][t] = v1.w;
    }
    __syncthreads();
    int h = tid >> 4, c = (tid & 15) * 8;
    uint4 hiv, lov;
    uint32_t* hp = (uint32_t*)&hiv;
    uint32_t* lp = (uint32_t*)&lov;
    #pragma unroll
    for (int e = 0; e < 4; e++) {
        float x = ts[h][c + 2 * e], y = ts[h][c + 2 * e + 1];
        __nv_bfloat16 hx = __float2bfloat16(x), hy = __float2bfloat16(y);
        hp[e] = pkbf(x, y);
        lp[e] = pkbf(x - __bfloat162float(hx), y - __bfloat162float(hy));
    }
    size_t dst = hb + (size_t)h * TT + t0 + c;
    *(uint4*)&g_vthi[dst] = hiv;
    *(uint4*)&g_vtlo[dst] = lov;
}

// ---------------- mma.sync GEMM + YAT epilogue (now 2 CTAs/SM) ----------------
#define GBK 32
#define ROWPAD 40
#define TILE_B (128*ROWPAD*2)
#define BUF_B  (4*TILE_B)
#define GDYN   (2*BUF_B)

__global__ __launch_bounds__(256, 2)
void gemm_mma_kernel(const __nv_bfloat16* __restrict__ Ahi, const __nv_bfloat16* __restrict__ Alo,
                     const __nv_bfloat16* __restrict__ BhiT, const __nv_bfloat16* __restrict__ BloT,
                     const float* __restrict__ x2, const float* __restrict__ k2,
                     const float* __restrict__ bias, const float* __restrict__ alpha,
                     int N, int mode, float* __restrict__ outP) {
    extern __shared__ char smem[];
    const uint32_t sb = smem_u32(smem);
    const int tid = threadIdx.x;
    const int wid = tid >> 5, lane = tid & 31;
    const int wr = wid >> 2, wc = wid & 3;
    const int m0 = blockIdx.y * 128, n0 = blockIdx.x * 128;

    const __nv_bfloat16* srcs[4] = {
        Ahi + (size_t)m0 * CC, Alo + (size_t)m0 * CC,
        BhiT + (size_t)n0 * CC, BloT + (size_t)n0 * CC };

    float acc[4][4][4];
    #pragma unroll
    for (int i = 0; i < 4; i++)
        #pragma unroll
        for (int j = 0; j < 4; j++)
            #pragma unroll
            for (int e = 0; e < 4; e++) acc[i][j][e] = 0.f;

    const int grp = lane >> 3;
    const uint32_t aRow = (uint32_t)((wr*64 + (grp&1)*8 + (lane&7)) * (ROWPAD*2) + (grp>>1)*16);
    const uint32_t bRow = (uint32_t)((wc*32 + (grp>>1)*8 + (lane&7)) * (ROWPAD*2) + (grp&1)*16);

    const int NT = CC / GBK;

    {
        const uint32_t bufb = sb;
        #pragma unroll
        for (int t4 = 0; t4 < 4; t4++) {
            #pragma unroll
            for (int i = 0; i < 2; i++) {
                int idx = tid + 256 * i;
                int r = idx >> 2, c = idx & 3;
                uint32_t dst = bufb + t4*TILE_B + (uint32_t)(r*(ROWPAD*2) + c*16);
                cp_async16(dst, srcs[t4] + (size_t)r * CC + c*8);
            }
        }
        cp_commit();
    }

    for (int kt = 0; kt < NT; kt++) {
        const uint32_t cur = sb + (kt & 1) * BUF_B;
        if (kt < NT - 1) {
            const uint32_t nxtb = sb + ((kt + 1) & 1) * BUF_B;
            const int k0 = (kt + 1) * GBK;
            #pragma unroll
            for (int t4 = 0; t4 < 4; t4++) {
                #pragma unroll
                for (int i = 0; i < 2; i++) {
                    int idx = tid + 256 * i;
                    int r = idx >> 2, c = idx & 3;
                    uint32_t dst = nxtb + t4*TILE_B + (uint32_t)(r*(ROWPAD*2) + c*16);
                    cp_async16(dst, srcs[t4] + (size_t)r * CC + k0 + c*8);
                }
            }
            cp_commit();
            cp_wait1();
        } else {
            cp_wait0();
        }
        __syncthreads();

        #pragma unroll
        for (int k16 = 0; k16 < 2; k16++) {
            const uint32_t ko = (uint32_t)(k16 * 32);
            uint32_t ah[4][4], al[4][4], bh[2][4], bl[2][4];
            #pragma unroll
            for (int mt = 0; mt < 4; mt++) {
                ldsm4(ah[mt], cur + 0*TILE_B + aRow + (uint32_t)(mt*16*(ROWPAD*2)) + ko);
                ldsm4(al[mt], cur + 1*TILE_B + aRow + (uint32_t)(mt*16*(ROWPAD*2)) + ko);
            }
            #pragma unroll
            for (int nt = 0; nt < 2; nt++) {
                ldsm4(bh[nt], cur + 2*TILE_B + bRow + (uint32_t)(nt*16*(ROWPAD*2)) + ko);
                ldsm4(bl[nt], cur + 3*TILE_B + bRow + (uint32_t)(nt*16*(ROWPAD*2)) + ko);
            }
            #pragma unroll
            for (int mt = 0; mt < 4; mt++) {
                #pragma unroll
                for (int nt = 0; nt < 4; nt++) {
                    const uint32_t* bhp = &bh[nt >> 1][(nt & 1) * 2];
                    const uint32_t* blp = &bl[nt >> 1][(nt & 1) * 2];
                    mma16816(acc[mt][nt], ah[mt], bhp);
                    mma16816(acc[mt][nt], ah[mt], blp);
                    mma16816(acc[mt][nt], al[mt], bhp);
                }
            }
        }
        __syncthreads();
    }

    const float scale = powf(sqrtf((float)N) / log1pf((float)N), alpha[0]);
    const int mbase = m0 + wr*64 + (lane >> 2);
    const int nbase = n0 + wc*32 + (lane & 3)*2;

    #pragma unroll
    for (int mt = 0; mt < 4; mt++) {
        #pragma unroll
        for (int half = 0; half < 2; half++) {
            const int gm = mbase + mt*16 + half*8;
            const float x2v = x2[gm];
            const int bb = gm >> 10, t = gm & 1023;
            #pragma unroll
            for (int nt = 0; nt < 4; nt++) {
                float y0 = acc[mt][nt][half*2 + 0];
                float y1 = acc[mt][nt][half*2 + 1];
                const int gn = nbase + nt*8;
                float k20 = k2[gn], k21 = k2[gn+1];
                float b0 = bias[gn], b1 = bias[gn+1];
                float v0 = (y0*y0) / (x2v + k20 - 2.f*y0 + EPS_C) * scale + b0;
                float v1 = (y1*y1) / (x2v + k21 - 2.f*y1 + EPS_C) * scale + b1;
                if (mode == 0) {
                    #pragma unroll
                    for (int e = 0; e < 2; e++) {
                        int g = gn + e;
                        float val = e ? v1 : v0;
                        int s = g >> 10;
                        int hh = (g & 1023) >> 6;
                        int dd = g & 63;
                        size_t idx = (((size_t)(bb * NHEADS_EFF + dd) * TT) + t) * HD_EFF + hh;
                        if (s == 0) g_q[idx] = val;
                        else if (s == 1) g_k[idx] = val;
                        else g_v[idx] = val;
                    }
                } else {
                    float2 o; o.x = v0; o.y = v1;
                    *(float2*)(outP + (size_t)gm * N + gn) = o;
                }
            }
        }
    }
}

// ---------------- tensor-core attention ----------------
__global__ __launch_bounds__(256, 2)
void attn_mma_kernel(const float* __restrict__ alpha_attn) {
    __shared__ __nv_bfloat16 Kh[128*24];
    __shared__ __nv_bfloat16 Kl[128*24];
    __shared__ __nv_bfloat16 VTh[16*136];
    __shared__ __nv_bfloat16 VTl[16*136];
    __shared__ float k2s[128];

    const int tid = threadIdx.x, lane = tid & 31, wr = tid >> 5;
    const int g = lane >> 2, tc = lane & 3;
    const int itile = blockIdx.x, dh = blockIdx.y, b = blockIdx.z;
    const int i0 = itile * 128;
    const size_t hb = (size_t)(b * NHEADS_EFF + dh) * TT * HD_EFF;
    const size_t nb = (size_t)(b * NHEADS_EFF + dh) * TT;

    const float inv_scale = powf(64.0f / log1pf(64.0f), alpha_attn[0]);

    const int r0 = i0 + wr * 16 + g;

    uint32_t aq_h[4], aq_l[4];
    {
        const __nv_bfloat16* qh = g_qhi + hb;
        const __nv_bfloat16* ql = g_qlo + hb;
        aq_h[0] = *(const uint32_t*)&qh[(size_t)r0 * 16 + 2*tc];
        aq_h[1] = *(const uint32_t*)&qh[(size_t)(r0+8) * 16 + 2*tc];
        aq_h[2] = *(const uint32_t*)&qh[(size_t)r0 * 16 + 8 + 2*tc];
        aq_h[3] = *(const uint32_t*)&qh[(size_t)(r0+8) * 16 + 8 + 2*tc];
        aq_l[0] = *(const uint32_t*)&ql[(size_t)r0 * 16 + 2*tc];
        aq_l[1] = *(const uint32_t*)&ql[(size_t)(r0+8) * 16 + 2*tc];
        aq_l[2] = *(const uint32_t*)&ql[(size_t)r0 * 16 + 8 + 2*tc];
        aq_l[3] = *(const uint32_t*)&ql[(size_t)(r0+8) * 16 + 8 + 2*tc];
    }
    const float q20 = g_qq[nb + r0] + EPS_C;
    const float q21 = g_qq[nb + r0 + 8] + EPS_C;

    float O0[8];
    #pragma unroll
    for (int e = 0; e < 8; e++) O0[e] = 0.f;
    float l0 = 0.f, l1 = 0.f;

    for (int jt = 0; jt <= itile; jt++) {
        const int j0 = jt * 128;
        __syncthreads();
        {
            int row = tid >> 1, hcol = (tid & 1) * 8;
            *(uint4*)&Kh[row*24 + hcol] = *(const uint4*)&g_khi[hb + (size_t)(j0 + row)*16 + hcol];
            *(uint4*)&Kl[row*24 + hcol] = *(const uint4*)&g_klo[hb + (size_t)(j0 + row)*16 + hcol];
            int vrow = tid >> 4, vcol = (tid & 15) * 8;
            *(uint4*)&VTh[vrow*136 + vcol] = *(const uint4*)&g_vthi[hb + (size_t)vrow*TT + j0 + vcol];
            *(uint4*)&VTl[vrow*136 + vcol] = *(const uint4*)&g_vtlo[hb + (size_t)vrow*TT + j0 + vcol];
            if (tid < 128) k2s[tid] = g_kk[nb + j0 + tid];
        }
        __syncthreads();

        float S[16][4];
        #pragma unroll
        for (int nt = 0; nt < 16; nt++) {
            uint32_t bh[2], bl[2];
            int kr = (nt*8 + g) * 24 + 2*tc;
            bh[0] = *(const uint32_t*)&Kh[kr];
            bh[1] = *(const uint32_t*)&Kh[kr + 8];
            bl[0] = *(const uint32_t*)&Kl[kr];
            bl[1] = *(const uint32_t*)&Kl[kr + 8];
            S[nt][0] = S[nt][1] = S[nt][2] = S[nt][3] = 0.f;
            mma16816(S[nt], aq_h, bh);
            mma16816(S[nt], aq_h, bl);
            mma16816(S[nt], aq_l, bh);
        }

        const bool maskt = (jt == itile);
        #pragma unroll
        for (int nt = 0; nt < 16; nt++) {
            #pragma unroll
            for (int c = 0; c < 4; c++) {
                float s = S[nt][c];
                float k2v = k2s[nt*8 + 2*tc + (c & 1)];
                float q2v = (c < 2) ? q20 : q21;
                float den = fmaf(-2.f, s, q2v + k2v);
                float p = __expf(__fdividef(s * s * inv_scale, den));
                if (maskt) {
                    int j = j0 + nt*8 + 2*tc + (c & 1);
                    int iq = (c < 2) ? r0 : r0 + 8;
                    if (j > iq) p = 0.f;
                }
                if (c < 2) l0 += p; else l1 += p;
                S[nt][c] = p;
            }
        }

        #pragma unroll
        for (int kb = 0; kb < 8; kb++) {
            float* Sa = S[2*kb];
            float* Sb = S[2*kb + 1];
            uint32_t ph[4], pl[4];
            ph[0] = pkbf(Sa[0], Sa[1]);
            ph[1] = pkbf(Sa[2], Sa[3]);
            ph[2] = pkbf(Sb[0], Sb[1]);
            ph[3] = pkbf(Sb[2], Sb[3]);
            float2 f;
            f = ubf(ph[0]); pl[0] = pkbf(Sa[0] - f.x, Sa[1] - f.y);
            f = ubf(ph[1]); pl[1] = pkbf(Sa[2] - f.x, Sa[3] - f.y);
            f = ubf(ph[2]); pl[2] = pkbf(Sb[0] - f.x, Sb[1] - f.y);
            f = ubf(ph[3]); pl[3] = pkbf(Sb[2] - f.x, Sb[3] - f.y);
            #pragma unroll
            for (int dt = 0; dt < 2; dt++) {
                uint32_t bvh[2], bvl[2];
                int vr = (dt*8 + g) * 136 + kb*16 + 2*tc;
                bvh[0] = *(const uint32_t*)&VTh[vr];
                bvh[1] = *(const uint32_t*)&VTh[vr + 8];
                bvl[0] = *(const uint32_t*)&VTl[vr];
                bvl[1] = *(const uint32_t*)&VTl[vr + 8];
                float* Od = &O0[dt*4];
                mma16816(Od, ph, bvh);
                mma16816(Od, ph, bvl);
                mma16816(Od, pl, bvh);
            }
        }
    }

    l0 += __shfl_xor_sync(~0u, l0, 1); l0 += __shfl_xor_sync(~0u, l0, 2);
    l1 += __shfl_xor_sync(~0u, l1, 1); l1 += __shfl_xor_sync(~0u, l1, 2);
    const float inv0 = 1.f / l0, inv1 = 1.f / l1;

    float* ob0 = g_att + (size_t)(b*TT + r0) * CC + dh*16;
    float* ob1 = g_att + (size_t)(b*TT + r0 + 8) * CC + dh*16;
    #pragma unroll
    for (int dt = 0; dt < 2; dt++) {
        int col = dt*8 + 2*tc;
        float2 o0; o0.x = O0[dt*4+0]*inv0; o0.y = O0[dt*4+1]*inv0;
        float2 o1; o1.x = O0[dt*4+2]*inv1; o1.y = O0[dt*4+3]*inv1;
        *(float2*)&ob0[col] = o0;
        *(float2*)&ob1[col] = o1;
    }
}

// ---------------- launch ----------------
extern "C" void kernel_launch(void* const* d_in, const int* in_sizes, int n_in,
                              void* d_out, int out_size) {
    const float* x          = (const float*)d_in[0];
    const float* w_qkv      = (const float*)d_in[2];
    const float* b_qkv      = (const float*)d_in[3];
    const float* alpha_qkv  = (const float*)d_in[4];
    const float* w_proj     = (const float*)d_in[5];
    const float* b_proj     = (const float*)d_in[6];
    const float* alpha_proj = (const float*)d_in[7];
    const float* alpha_attn = (const float*)d_in[8];
    float* out = (float*)d_out;

    void *p_att, *p_x2a, *p_x2b, *p_k2a, *p_k2b;
    void *p_ahi, *p_alo, *p_bqhi, *p_bqlo, *p_bphi, *p_bplo;
    cudaGetSymbolAddress(&p_att,  g_att);
    cudaGetSymbolAddress(&p_x2a,  g_x2a);
    cudaGetSymbolAddress(&p_x2b,  g_x2b);
    cudaGetSymbolAddress(&p_k2a,  g_k2a);
    cudaGetSymbolAddress(&p_k2b,  g_k2b);
    cudaGetSymbolAddress(&p_ahi,  g_ahi);
    cudaGetSymbolAddress(&p_alo,  g_alo);
    cudaGetSymbolAddress(&p_bqhi, g_bqhi);
    cudaGetSymbolAddress(&p_bqlo, g_bqlo);
    cudaGetSymbolAddress(&p_bphi, g_bphi);
    cudaGetSymbolAddress(&p_bplo, g_bplo);

    cudaFuncSetAttribute(gemm_mma_kernel, cudaFuncAttributeMaxDynamicSharedMemorySize, GDYN);

    // (1) fused x row-norms + split (+ zero colnorm accumulators)
    rowsplit_kernel<<<MROWS, 256>>>(x, (float*)p_x2a,
                                    (__nv_bfloat16*)p_ahi, (__nv_bfloat16*)p_alo, 1);
    // (2) w_qkv transpose+split+colnorm
    {
        dim3 g(F_QKV / 32, CC / 32);
        tsplit_kernel<<<g, 256>>>(w_qkv, F_QKV, (__nv_bfloat16*)p_bqhi, (__nv_bfloat16*)p_bqlo,
                                  (float*)p_k2a);
    }
    // (3) w_proj transpose+split+colnorm
    {
        dim3 g(CC / 32, CC / 32);
        tsplit_kernel<<<g, 256>>>(w_proj, CC, (__nv_bfloat16*)p_bphi, (__nv_bfloat16*)p_bplo,
                                  (float*)p_k2b);
    }
    // (4) qkv GEMM  <-- profiled launch
    {
        dim3 grid(F_QKV / 128, MROWS / 128);
        gemm_mma_kernel<<<grid, 256, GDYN>>>(
            (const __nv_bfloat16*)p_ahi, (const __nv_bfloat16*)p_alo,
            (const __nv_bfloat16*)p_bqhi, (const __nv_bfloat16*)p_bqlo,
            (const float*)p_x2a, (const float*)p_k2a, b_qkv, alpha_qkv,
            F_QKV, 0, nullptr);
    }
    // (5) fused q/k norms + splits
    qkprep2_kernel<<<(BATCH * NHEADS_EFF * TT) / 256, 256>>>();
    // (6) v transpose + split
    {
        dim3 gv(TT / 128, NHEADS_EFF, BATCH);
        vtsplit_kernel<<<gv, 256>>>();
    }
    // (7) attention
    {
        dim3 grid(TT / 128, NHEADS_EFF, BATCH);
        attn_mma_kernel<<<grid, 256>>>(alpha_attn);
    }
    // (8) fused att row-norms + split
    rowsplit_kernel<<<MROWS, 256>>>((const float*)p_att, (float*)p_x2b,
                                    (__nv_bfloat16*)p_ahi, (__nv_bfloat16*)p_alo, 0);
    // (9) proj GEMM
    {
        dim3 grid(CC / 128, MROWS / 128);
        gemm_mma_kernel<<<grid, 256, GDYN>>>(
            (const __nv_bfloat16*)p_ahi, (const __nv_bfloat16*)p_alo,
            (const __nv_bfloat16*)p_bphi, (const __nv_bfloat16*)p_bplo,
            (const float*)p_x2b, (const float*)p_k2b, b_proj, alpha_proj,
            CC, 1, out);
    }
}